// round 3
// baseline (speedup 1.0000x reference)
#include <cuda_runtime.h>
#include <math.h>

#define BSZ 4
#define CCH 12
#define HH 384
#define WW 384
#define HW (HH*WW)
#define NN 4096
#define NHID 64

// ---------------- static device scratch (no allocs allowed) ----------------
__device__ float  g_h1[BSZ*64*HW];          // conv1 out  (151MB)
__device__ float  g_h2[BSZ*64*HW];          // conv2 out  (151MB)
__device__ float  g_tmp2[BSZ*2*HW];         // conv3 out
__device__ float  g_s [2*NN*BSZ*NHID];      // [c][m][b*64]
__device__ float  g_g [2*NN*BSZ*NHID];      // relu(adj@s)
__device__ float  g_s3[2*NN*BSZ*36];        // [c][m][b*36]
__device__ float  g_t3[2*NN*BSZ*36];        // adj@s3
__device__ float  g_oimg[BSZ*2*HW];         // combined image
__device__ float2 g_k[CCH*BSZ*HW];          // complex k-space work (56.6MB)
__device__ float2 g_tw128[64];
__device__ float2 g_tw384[384];

// ---------------- twiddle init ----------------
__global__ void init_tw_k() {
    int t = threadIdx.x;
    if (t < 64) {
        float s, c; sincospif(-(float)t / 64.f, &s, &c);   // exp(-2*pi*i*t/128)
        g_tw128[t] = make_float2(c, s);
    }
    {
        float s, c; sincospif(-(float)t / 192.f, &s, &c);  // exp(-2*pi*i*t/384)
        g_tw384[t] = make_float2(c, s);
    }
}

// ---------------- conv1: 2 -> 64, relu ----------------
__global__ __launch_bounds__(256) void conv1_k(const float* __restrict__ in,
                                               const float* __restrict__ w,
                                               const float* __restrict__ bias) {
    __shared__ float ws[18 * 64];   // transposed: [q=ci*9+tap][co]
    for (int i = threadIdx.x; i < 1152; i += 256) {
        int co = i / 18, q = i % 18;
        ws[q * 64 + co] = w[i];
    }
    __syncthreads();
    int p = blockIdx.x * 256 + threadIdx.x;       // exact: 589824 total
    int x = p % WW, y = (p / WW) % HH, b = p / HW;
    float acc[64];
#pragma unroll
    for (int co = 0; co < 64; co++) acc[co] = __ldg(bias + co);
    for (int ci = 0; ci < 2; ci++) {
        const float* base = in + (b * 2 + ci) * HW;
#pragma unroll
        for (int ky = 0; ky < 3; ky++) {
            int yy = y + ky - 1; bool yok = (unsigned)yy < HH;
#pragma unroll
            for (int kx = 0; kx < 3; kx++) {
                int xx = x + kx - 1;
                float v = (yok && (unsigned)xx < WW) ? __ldg(base + yy * WW + xx) : 0.f;
                const float* wr = &ws[(ci * 9 + ky * 3 + kx) * 64];
#pragma unroll
                for (int co = 0; co < 64; co++) acc[co] += v * wr[co];
            }
        }
    }
    float* ob = g_h1 + (size_t)b * 64 * HW + y * WW + x;
#pragma unroll
    for (int co = 0; co < 64; co++) ob[(size_t)co * HW] = fmaxf(acc[co], 0.f);
}

// ---------------- conv2: 64 -> 64, relu (the heavy one) ----------------
__global__ __launch_bounds__(256) void conv2_k(const float* __restrict__ w,
                                               const float* __restrict__ bias) {
    __shared__ float ws[16 * 9 * 64];   // [cl*9+t][co], one 16-ci chunk
    int lx = threadIdx.x & 31, ly = threadIdx.x >> 5;
    int x = blockIdx.x * 32 + lx, y = blockIdx.y * 8 + ly, b = blockIdx.z;
    float acc[64];
#pragma unroll
    for (int co = 0; co < 64; co++) acc[co] = __ldg(bias + co);
    for (int ch = 0; ch < 4; ch++) {
        int ci0 = ch * 16;
        __syncthreads();
        for (int i = threadIdx.x; i < 9216; i += 256) {
            int cl = i / 576, rem = i % 576, t = rem >> 6, co = rem & 63;
            ws[i] = __ldg(w + co * 576 + (ci0 + cl) * 9 + t);
        }
        __syncthreads();
        for (int cl = 0; cl < 16; cl++) {
            const float* hb = g_h1 + (size_t)(b * 64 + ci0 + cl) * HW;
            float v[9];
#pragma unroll
            for (int ky = 0; ky < 3; ky++) {
                int yy = y + ky - 1; bool yok = (unsigned)yy < HH;
#pragma unroll
                for (int kx = 0; kx < 3; kx++) {
                    int xx = x + kx - 1;
                    v[ky * 3 + kx] = (yok && (unsigned)xx < WW) ? __ldg(hb + yy * WW + xx) : 0.f;
                }
            }
#pragma unroll
            for (int t = 0; t < 9; t++) {
                float vt = v[t];
                const float* wr = &ws[(cl * 9 + t) * 64];
#pragma unroll
                for (int co = 0; co < 64; co++) acc[co] += vt * wr[co];
            }
        }
    }
    float* ob = g_h2 + (size_t)b * 64 * HW + y * WW + x;
#pragma unroll
    for (int co = 0; co < 64; co++) ob[(size_t)co * HW] = fmaxf(acc[co], 0.f);
}

// ---------------- conv3: 64 -> 2 ----------------
__global__ __launch_bounds__(256) void conv3_k(const float* __restrict__ w,
                                               const float* __restrict__ bias) {
    __shared__ float ws[1152];      // [o][ci][tap] as-is
    for (int i = threadIdx.x; i < 1152; i += 256) ws[i] = w[i];
    __syncthreads();
    int p = blockIdx.x * 256 + threadIdx.x;
    int x = p % WW, y = (p / WW) % HH, b = p / HW;
    float a0 = __ldg(bias + 0), a1 = __ldg(bias + 1);
    for (int ci = 0; ci < 64; ci++) {
        const float* hb = g_h2 + (size_t)(b * 64 + ci) * HW;
#pragma unroll
        for (int ky = 0; ky < 3; ky++) {
            int yy = y + ky - 1; bool yok = (unsigned)yy < HH;
#pragma unroll
            for (int kx = 0; kx < 3; kx++) {
                int xx = x + kx - 1;
                float v = (yok && (unsigned)xx < WW) ? __ldg(hb + yy * WW + xx) : 0.f;
                int t = ky * 3 + kx;
                a0 += v * ws[ci * 9 + t];
                a1 += v * ws[576 + ci * 9 + t];
            }
        }
    }
    g_tmp2[(b * 2 + 0) * HW + y * WW + x] = a0;
    g_tmp2[(b * 2 + 1) * HW + y * WW + x] = a1;
}

// ---------------- GCN: s = feat @ W1   (layout [c][m][b*64]) ----------------
__global__ __launch_bounds__(128) void gcn_s_k(const float* __restrict__ in,
                                               const float* __restrict__ W1) {
    __shared__ float w[36 * 64];
    for (int i = threadIdx.x; i < 2304; i += 128) w[i] = W1[i];
    __syncthreads();
    int idx = blockIdx.x * 128 + threadIdx.x;   // 32768 total
    int n = idx & 4095, b = (idx >> 12) & 3, c = idx >> 14;
    int gy = n >> 6, gx = n & 63;
    const float* base = in + (b * 2 + c) * HW + (gy * 6) * WW + gx * 6;
    float f[36];
#pragma unroll
    for (int py = 0; py < 6; py++)
#pragma unroll
        for (int px = 0; px < 6; px++) f[py * 6 + px] = __ldg(base + py * WW + px);
    float acc[64];
#pragma unroll
    for (int o = 0; o < 64; o++) acc[o] = 0.f;
#pragma unroll
    for (int ff = 0; ff < 36; ff++) {
        float fv = f[ff];
        const float* wr = &w[ff * 64];
#pragma unroll
        for (int o = 0; o < 64; o++) acc[o] += fv * wr[o];
    }
    float* ob = g_s + ((size_t)(c * NN + n) * BSZ + b) * 64;
#pragma unroll
    for (int o = 0; o < 64; o++) ob[o] = acc[o];
}

// ---------------- GCN: s3 = g @ W3   (layout [c][m][b*36]) ----------------
__global__ __launch_bounds__(128) void gcn_s3_k(const float* __restrict__ W3) {
    __shared__ float w[64 * 36];
    for (int i = threadIdx.x; i < 2304; i += 128) w[i] = W3[i];
    __syncthreads();
    int idx = blockIdx.x * 128 + threadIdx.x;
    int n = idx & 4095, b = (idx >> 12) & 3, c = idx >> 14;
    const float* gb = g_g + ((size_t)(c * NN + n) * BSZ + b) * 64;
    float acc[36];
#pragma unroll
    for (int o = 0; o < 36; o++) acc[o] = 0.f;
#pragma unroll
    for (int k = 0; k < 64; k++) {
        float gv = gb[k];
        const float* wr = &w[k * 36];
#pragma unroll
        for (int o = 0; o < 36; o++) acc[o] += gv * wr[o];
    }
    float* ob = g_s3 + ((size_t)(c * NN + n) * BSZ + b) * 36;
#pragma unroll
    for (int o = 0; o < 36; o++) ob[o] = acc[o];
}

// ---------------- tiled fp32 GEMM: C[c] = (relu?)(adj[c] @ B[c]) ----------------
// mode 0: B=g_s  (Nc=256), C=g_g, relu.  mode 1: B=g_s3 (Nc=144), C=g_t3.
__global__ __launch_bounds__(256) void gemm_k(const float* __restrict__ A0, int Nc, int mode) {
    const float* Bm; float* Cm;
    if (mode == 0) { Bm = g_s  + (size_t)blockIdx.z * NN * 256; Cm = g_g  + (size_t)blockIdx.z * NN * 256; }
    else           { Bm = g_s3 + (size_t)blockIdx.z * NN * 144; Cm = g_t3 + (size_t)blockIdx.z * NN * 144; }
    const float* A = A0 + (size_t)blockIdx.z * NN * NN;
    const int K = NN;
    __shared__ float As[8][128];
    __shared__ float Bs[8][128];
    int tid = threadIdx.x, tx = tid & 15, ty = tid >> 4;
    int m0 = blockIdx.y * 128, n0 = blockIdx.x * 128;
    float acc[8][8];
#pragma unroll
    for (int i = 0; i < 8; i++)
#pragma unroll
        for (int j = 0; j < 8; j++) acc[i][j] = 0.f;
    int a_m = tid >> 1, a_k = (tid & 1) * 4;
    int b_k = tid >> 5, b_n = (tid & 31) * 4;
    for (int k0 = 0; k0 < K; k0 += 8) {
        float4 av = *(const float4*)(A + (size_t)(m0 + a_m) * K + k0 + a_k);
        As[a_k + 0][a_m] = av.x; As[a_k + 1][a_m] = av.y;
        As[a_k + 2][a_m] = av.z; As[a_k + 3][a_m] = av.w;
        int gn = n0 + b_n;
        const float* bp = Bm + (size_t)(k0 + b_k) * Nc;
        float4 bv;
        if (gn + 3 < Nc) bv = *(const float4*)(bp + gn);
        else {
            bv.x = (gn + 0 < Nc) ? bp[gn + 0] : 0.f;
            bv.y = (gn + 1 < Nc) ? bp[gn + 1] : 0.f;
            bv.z = (gn + 2 < Nc) ? bp[gn + 2] : 0.f;
            bv.w = (gn + 3 < Nc) ? bp[gn + 3] : 0.f;
        }
        Bs[b_k][b_n + 0] = bv.x; Bs[b_k][b_n + 1] = bv.y;
        Bs[b_k][b_n + 2] = bv.z; Bs[b_k][b_n + 3] = bv.w;
        __syncthreads();
#pragma unroll
        for (int kk = 0; kk < 8; kk++) {
            float a8[8], b8[8];
#pragma unroll
            for (int i = 0; i < 8; i++) a8[i] = As[kk][ty * 8 + i];
#pragma unroll
            for (int j = 0; j < 8; j++) b8[j] = Bs[kk][tx * 8 + j];
#pragma unroll
            for (int i = 0; i < 8; i++)
#pragma unroll
                for (int j = 0; j < 8; j++) acc[i][j] += a8[i] * b8[j];
        }
        __syncthreads();
    }
#pragma unroll
    for (int i = 0; i < 8; i++) {
        int gm = m0 + ty * 8 + i;
#pragma unroll
        for (int j = 0; j < 8; j++) {
            int gn = n0 + tx * 8 + j;
            if (gn < Nc) {
                float v = acc[i][j];
                if (mode == 0) v = fmaxf(v, 0.f);
                Cm[(size_t)gm * Nc + gn] = v;
            }
        }
    }
}

// ---------------- combine: out = in + (1-arf)*tmp2 + arf*tmp3 ----------------
__global__ __launch_bounds__(256) void combine_k(const float* __restrict__ in,
                                                 const float* __restrict__ arf) {
    int g = blockIdx.x * 256 + threadIdx.x;   // b*HW + p
    int p = g % HW, b = g / HW;
    int x = p % WW, y = p / WW;
    float a = __ldg(arf);
    int gy = y / 6, py = y - gy * 6, gx = x / 6, px = x - gx * 6;
    int n = gy * 64 + gx, f = py * 6 + px;
#pragma unroll
    for (int c = 0; c < 2; c++) {
        float t3v = g_t3[(size_t)(c * NN + n) * 144 + b * 36 + f];
        int li = (b * 2 + c) * HW + p;
        g_oimg[li] = in[li] + (1.f - a) * g_tmp2[li] + a * t3v;
    }
}

// ---------------- z = (-1)^(x+y) * (out_complex * csm) ----------------
__global__ __launch_bounds__(256) void zmake_k(const float* __restrict__ csr,
                                               const float* __restrict__ csi) {
    int idx = blockIdx.x * 256 + threadIdx.x;   // (c*B+b)*HW + p
    int p = idx % HW, cb = idx / HW;
    int b = cb & 3, c = cb >> 2;
    int x = p % WW, y = p / WW;
    float sgn = ((x + y) & 1) ? -1.f : 1.f;
    float orr = g_oimg[(b * 2 + 0) * HW + p];
    float oii = g_oimg[(b * 2 + 1) * HW + p];
    float cr = __ldg(csr + (size_t)(b * CCH + c) * HW + p);
    float ci = __ldg(csi + (size_t)(b * CCH + c) * HW + p);
    g_k[idx] = make_float2(sgn * (orr * cr - oii * ci), sgn * (orr * ci + oii * cr));
}

// ---------------- complex helpers ----------------
__device__ __forceinline__ float2 cadd(float2 a, float2 b) { return make_float2(a.x + b.x, a.y + b.y); }
__device__ __forceinline__ float2 csub(float2 a, float2 b) { return make_float2(a.x - b.x, a.y - b.y); }

// ---------------- row FFT (length 384 = 3 x radix-2-128), in-place ----------------
template<int INV>
__global__ __launch_bounds__(192) void fft_row_k() {
    __shared__ float2 sb[384];
    float2* base = g_k + (size_t)blockIdx.x * 384;   // [48*384] lines
    int tid = threadIdx.x;
    for (int i = tid; i < 384; i += 192) {
        int r = i % 3, q = i / 3;
        sb[r * 128 + q] = base[i];
    }
    __syncthreads();
    int r = tid >> 6, bf = tid & 63, off = r << 7;
#pragma unroll
    for (int len = 128; len >= 2; len >>= 1) {
        int h = len >> 1;
        int grp = bf / h, t = bf - grp * h;
        int i1 = off + grp * len + t;
        float2 u = sb[i1], v = sb[i1 + h];
        sb[i1] = cadd(u, v);
        float2 d = csub(u, v);
        float2 w = g_tw128[t * (128 / len)];
        float wy = INV ? -w.y : w.y;
        sb[i1 + h] = make_float2(d.x * w.x - d.y * wy, d.x * wy + d.y * w.x);
        __syncthreads();
    }
    for (int k = tid; k < 384; k += 192) {
        int k0 = k & 127;
        int rv = __brev((unsigned)k0) >> 25;
        float2 y0 = sb[rv], y1 = sb[128 + rv], y2 = sb[256 + rv];
        float2 c1 = g_tw384[k], c2 = g_tw384[(2 * k) % 384];
        float s1 = INV ? -c1.y : c1.y, s2 = INV ? -c2.y : c2.y;
        float xr = y0.x + c1.x * y1.x - s1 * y1.y + c2.x * y2.x - s2 * y2.y;
        float xi = y0.y + c1.x * y1.y + s1 * y1.x + c2.x * y2.y + s2 * y2.x;
        if (INV) { xr *= (1.f / 384.f); xi *= (1.f / 384.f); }
        base[k] = make_float2(xr, xi);
    }
}

// ---------------- column FFT: 8 columns / block, in-place ----------------
template<int INV>
__global__ __launch_bounds__(192) void fft_col_k() {
    __shared__ float2 sb[8 * 384];
    int img = blockIdx.x / 48, cg = blockIdx.x % 48;
    float2* base = g_k + (size_t)img * HW + cg * 8;
    int tid = threadIdx.x;
    for (int i = tid; i < 3072; i += 192) {
        int col = i & 7, yy = i >> 3;
        int r = yy % 3, q = yy / 3;
        sb[col * 384 + r * 128 + q] = base[(size_t)yy * 384 + col];
    }
    __syncthreads();
#pragma unroll
    for (int len = 128; len >= 2; len >>= 1) {
        int h = len >> 1;
        for (int widx = tid; widx < 1536; widx += 192) {
            int seg = widx >> 6, bf = widx & 63;
            int boff = (seg / 3) * 384 + (seg % 3) * 128;
            int grp = bf / h, t = bf - grp * h;
            int i1 = boff + grp * len + t;
            float2 u = sb[i1], v = sb[i1 + h];
            sb[i1] = cadd(u, v);
            float2 d = csub(u, v);
            float2 w = g_tw128[t * (128 / len)];
            float wy = INV ? -w.y : w.y;
            sb[i1 + h] = make_float2(d.x * w.x - d.y * wy, d.x * wy + d.y * w.x);
        }
        __syncthreads();
    }
    for (int i = tid; i < 3072; i += 192) {
        int col = i & 7, k = i >> 3;
        int k0 = k & 127;
        int rv = __brev((unsigned)k0) >> 25;
        int cb = col * 384;
        float2 y0 = sb[cb + rv], y1 = sb[cb + 128 + rv], y2 = sb[cb + 256 + rv];
        float2 c1 = g_tw384[k], c2 = g_tw384[(2 * k) % 384];
        float s1 = INV ? -c1.y : c1.y, s2 = INV ? -c2.y : c2.y;
        float xr = y0.x + c1.x * y1.x - s1 * y1.y + c2.x * y2.x - s2 * y2.y;
        float xi = y0.y + c1.x * y1.y + s1 * y1.x + c2.x * y2.y + s2 * y2.x;
        if (INV) { xr *= (1.f / 384.f); xi *= (1.f / 384.f); }
        base[(size_t)k * 384 + col] = make_float2(xr, xi);
    }
}

// ---------------- data consistency ----------------
__global__ __launch_bounds__(256) void dc_k(const int* __restrict__ mask,
                                            const float* __restrict__ tkr,
                                            const float* __restrict__ tki) {
    int idx = blockIdx.x * 256 + threadIdx.x;
    int p = idx % HW;
    int x = p % WW, y = p / WW;
    float m = (float)__ldg(mask + p);
    float sgn = ((x + y) & 1) ? -1.f : 1.f;
    float2 Z = g_k[idx];
    float coef = 384.f * 0.999999f * m * sgn;
    float om = 1.f - m;
    g_k[idx] = make_float2(om * Z.x + coef * __ldg(tkr + idx),
                           om * Z.y + coef * __ldg(tki + idx));
}

// ---------------- final coil combine ----------------
__global__ __launch_bounds__(256) void final_k(const float* __restrict__ csr,
                                               const float* __restrict__ csi,
                                               float* __restrict__ out) {
    int g = blockIdx.x * 256 + threadIdx.x;   // b*HW + p
    int p = g % HW, b = g / HW;
    int x = p % WW, y = p / WW;
    float sgn = ((x + y) & 1) ? -1.f : 1.f;
    float rr = 0.f, ri = 0.f;
#pragma unroll
    for (int c = 0; c < CCH; c++) {
        float2 z = g_k[(size_t)(c * BSZ + b) * HW + p];
        float cr = __ldg(csr + (size_t)(b * CCH + c) * HW + p);
        float ci = __ldg(csi + (size_t)(b * CCH + c) * HW + p);
        rr += z.x * cr + z.y * ci;     // z * conj(csm)
        ri += z.y * cr - z.x * ci;
    }
    out[(b * 2 + 0) * HW + p] = sgn * rr;
    out[(b * 2 + 1) * HW + p] = sgn * ri;
}

// ---------------- launch ----------------
extern "C" void kernel_launch(void* const* d_in, const int* in_sizes, int n_in,
                              void* d_out, int out_size) {
    (void)in_sizes; (void)n_in; (void)out_size;
    const float* input = (const float*)d_in[0];
    const float* adj   = (const float*)d_in[1];
    const int*   mask  = (const int*)  d_in[2];
    const float* csr   = (const float*)d_in[3];
    const float* csi   = (const float*)d_in[4];
    const float* tkr   = (const float*)d_in[5];
    const float* tki   = (const float*)d_in[6];
    const float* W1    = (const float*)d_in[7];
    const float* W3    = (const float*)d_in[8];
    const float* arf   = (const float*)d_in[9];
    const float* cw1   = (const float*)d_in[10];
    const float* cb1   = (const float*)d_in[11];
    const float* cw2   = (const float*)d_in[12];
    const float* cb2   = (const float*)d_in[13];
    const float* cw3   = (const float*)d_in[14];
    const float* cb3   = (const float*)d_in[15];
    float* out = (float*)d_out;

    init_tw_k<<<1, 384>>>();

    // CNN branch
    conv1_k<<<2304, 256>>>(input, cw1, cb1);
    conv2_k<<<dim3(12, 48, 4), 256>>>(cw2, cb2);
    conv3_k<<<2304, 256>>>(cw3, cb3);

    // GCN branch
    gcn_s_k<<<256, 128>>>(input, W1);
    gemm_k<<<dim3(2, 32, 2), 256>>>(adj, 256, 0);   // g = relu(adj @ s)
    gcn_s3_k<<<256, 128>>>(W3);
    gemm_k<<<dim3(2, 32, 2), 256>>>(adj, 144, 1);   // t3 = adj @ s3

    // combine + data consistency
    combine_k<<<2304, 256>>>(input, arf);
    zmake_k<<<27648, 256>>>(csr, csi);
    fft_row_k<0><<<48 * 384, 192>>>();
    fft_col_k<0><<<48 * 48, 192>>>();
    dc_k<<<27648, 256>>>(mask, tkr, tki);
    fft_col_k<1><<<48 * 48, 192>>>();
    fft_row_k<1><<<48 * 384, 192>>>();
    final_k<<<2304, 256>>>(csr, csi, out);
}

// round 5
// speedup vs baseline: 1.6059x; 1.6059x over previous
#include <cuda_runtime.h>
#include <cuda_fp16.h>
#include <cuda_bf16.h>
#include <math.h>
#include <stdint.h>

#define BSZ 4
#define CCH 12
#define HH 384
#define WW 384
#define HW (HH*WW)
#define NN 4096

// ---------------- static device scratch (no allocs allowed) ----------------
__device__ __half         g_h1n[(size_t)BSZ*HW*64];   // conv1 out, NHWC fp16
__device__ __half         g_h2n[(size_t)BSZ*HW*64];   // conv2 out, NHWC fp16
__device__ __nv_bfloat16  g_adjb[(size_t)2*NN*NN];    // adj bf16
__device__ __half         g_w2t[9*64*64];             // conv2 w [tap][co][ci]
__device__ __half         g_w3t[9*8*64];              // conv3 w [tap][o pad8][ci]
__device__ __nv_bfloat16  g_st [(size_t)2*256*NN];    // s^T  [c][b*64+o][m]
__device__ __nv_bfloat16  g_s3t[(size_t)2*144*NN];    // s3^T [c][b*36+o][m]
__device__ float          g_g  [(size_t)2*NN*256];    // relu(adj@s) [c][m][256]
__device__ float          g_t3 [(size_t)2*NN*144];    // adj@s3 [c][m][144]
__device__ float          g_tmp2[BSZ*2*HW];
__device__ float          g_oimg[BSZ*2*HW];
__device__ float2         g_k[(size_t)CCH*BSZ*HW];
__device__ float2         g_tw128[64];
__device__ float2         g_tw384[384];

// ---------------- mma wrappers (m16n8k16, f32 accum) ----------------
__device__ __forceinline__ void mma_f16(float c[4], unsigned a0, unsigned a1,
                                        unsigned a2, unsigned a3,
                                        unsigned b0, unsigned b1) {
    asm volatile("mma.sync.aligned.m16n8k16.row.col.f32.f16.f16.f32 "
        "{%0,%1,%2,%3}, {%4,%5,%6,%7}, {%8,%9}, {%0,%1,%2,%3};"
        : "+f"(c[0]), "+f"(c[1]), "+f"(c[2]), "+f"(c[3])
        : "r"(a0), "r"(a1), "r"(a2), "r"(a3), "r"(b0), "r"(b1));
}
__device__ __forceinline__ void mma_bf16(float c[4], unsigned a0, unsigned a1,
                                         unsigned a2, unsigned a3,
                                         unsigned b0, unsigned b1) {
    asm volatile("mma.sync.aligned.m16n8k16.row.col.f32.bf16.bf16.f32 "
        "{%0,%1,%2,%3}, {%4,%5,%6,%7}, {%8,%9}, {%0,%1,%2,%3};"
        : "+f"(c[0]), "+f"(c[1]), "+f"(c[2]), "+f"(c[3])
        : "r"(a0), "r"(a1), "r"(a2), "r"(a3), "r"(b0), "r"(b1));
}

// ---------------- init: twiddles ----------------
__global__ void init_tw_k() {
    int t = threadIdx.x;
    if (t < 64) { float s, c; sincospif(-(float)t / 64.f, &s, &c);  g_tw128[t] = make_float2(c, s); }
    {            float s, c; sincospif(-(float)t / 192.f, &s, &c); g_tw384[t] = make_float2(c, s); }
}

// ---------------- weight repack: cw[co][ci][tap] -> [tap][co][ci] fp16 ----------------
__global__ void prep_w_k(const float* __restrict__ cw2, const float* __restrict__ cw3) {
    int i = blockIdx.x * 256 + threadIdx.x;
    if (i < 9 * 64 * 64) {
        int tap = i / 4096, r = i % 4096, co = r >> 6, ci = r & 63;
        g_w2t[i] = __float2half(cw2[(co * 64 + ci) * 9 + tap]);
    }
    if (i < 9 * 8 * 64) {
        int tap = i / 512, r = i % 512, o = r >> 6, ci = r & 63;
        g_w3t[i] = __float2half((o < 2) ? cw3[(o * 64 + ci) * 9 + tap] : 0.f);
    }
}

// ---------------- adj fp32 -> bf16 ----------------
__global__ __launch_bounds__(256) void adj_cvt_k(const float* __restrict__ adj) {
    size_t i = ((size_t)blockIdx.x * 256 + threadIdx.x) * 4;
    float4 v = *(const float4*)(adj + i);
    __nv_bfloat162* o = (__nv_bfloat162*)(g_adjb + i);
    o[0] = __floats2bfloat162_rn(v.x, v.y);
    o[1] = __floats2bfloat162_rn(v.z, v.w);
}

// ---------------- conv1: 2 -> 64, relu, NHWC fp16 out ----------------
__global__ __launch_bounds__(256) void conv1_k(const float* __restrict__ in,
                                               const float* __restrict__ w,
                                               const float* __restrict__ bias) {
    __shared__ float ws[18 * 64];   // [q=ci*9+tap][co]
    for (int i = threadIdx.x; i < 1152; i += 256) {
        int co = i / 18, q = i % 18;
        ws[q * 64 + co] = w[i];
    }
    __syncthreads();
    int p = blockIdx.x * 256 + threadIdx.x;
    int x = p % WW, y = (p / WW) % HH, b = p / HW;
    float acc[64];
#pragma unroll
    for (int co = 0; co < 64; co++) acc[co] = __ldg(bias + co);
    for (int ci = 0; ci < 2; ci++) {
        const float* base = in + (b * 2 + ci) * HW;
#pragma unroll
        for (int ky = 0; ky < 3; ky++) {
            int yy = y + ky - 1; bool yok = (unsigned)yy < HH;
#pragma unroll
            for (int kx = 0; kx < 3; kx++) {
                int xx = x + kx - 1;
                float v = (yok && (unsigned)xx < WW) ? __ldg(base + yy * WW + xx) : 0.f;
                const float* wr = &ws[(ci * 9 + ky * 3 + kx) * 64];
#pragma unroll
                for (int co = 0; co < 64; co++) acc[co] += v * wr[co];
            }
        }
    }
    __half* ob = g_h1n + ((size_t)p) * 64;
#pragma unroll
    for (int co = 0; co < 64; co += 2)
        *(__half2*)(ob + co) = __floats2half2_rn(fmaxf(acc[co], 0.f), fmaxf(acc[co + 1], 0.f));
}

// ---------------- conv2: 64 -> 64 via mma fp16, relu ----------------
// grid (3, 384, 4), 256 thr = 8 warps; block tile M=128 (x strip), N=64, K=9*64
__global__ __launch_bounds__(256) void conv2_mma(const float* __restrict__ bias) {
    int x0 = blockIdx.x * 128, y = blockIdx.y, b = blockIdx.z;
    int wid = threadIdx.x >> 5, lane = threadIdx.x & 31;
    int g = lane >> 2, t = lane & 3;
    int m = wid * 16 + g;
    float acc[8][4];
#pragma unroll
    for (int i = 0; i < 8; i++)
#pragma unroll
        for (int j = 0; j < 4; j++) acc[i][j] = 0.f;
#pragma unroll
    for (int ky = 0; ky < 3; ky++) {
        int yy = y + ky - 1;
        if ((unsigned)yy >= HH) continue;
        const __half* hrow = g_h1n + ((size_t)(b * HH + yy)) * WW * 64;
#pragma unroll
        for (int kx = 0; kx < 3; kx++) {
            int xb = x0 + kx - 1;
            const __half* wt = g_w2t + (ky * 3 + kx) * 4096;
            int x1 = xb + m, x2 = x1 + 8;
            bool ok1 = (unsigned)x1 < WW, ok2 = (unsigned)x2 < WW;
            const __half* p1 = hrow + (size_t)x1 * 64;
            const __half* p2 = hrow + (size_t)x2 * 64;
#pragma unroll
            for (int kk = 0; kk < 4; kk++) {
                int ci = kk * 16 + 2 * t;
                unsigned a0 = ok1 ? *(const unsigned*)(p1 + ci) : 0u;
                unsigned a1 = ok2 ? *(const unsigned*)(p2 + ci) : 0u;
                unsigned a2 = ok1 ? *(const unsigned*)(p1 + ci + 8) : 0u;
                unsigned a3 = ok2 ? *(const unsigned*)(p2 + ci + 8) : 0u;
#pragma unroll
                for (int nt = 0; nt < 8; nt++) {
                    const __half* wn = wt + (nt * 8 + g) * 64 + ci;
                    unsigned b0 = *(const unsigned*)(wn);
                    unsigned b1 = *(const unsigned*)(wn + 8);
                    mma_f16(acc[nt], a0, a1, a2, a3, b0, b1);
                }
            }
        }
    }
    int px1 = x0 + m;
    __half* o1 = g_h2n + ((size_t)(b * HH + y) * WW + px1) * 64;
    __half* o2 = o1 + 8 * 64;
#pragma unroll
    for (int nt = 0; nt < 8; nt++) {
        int n = nt * 8 + 2 * t;
        float b0 = __ldg(bias + n), b1 = __ldg(bias + n + 1);
        *(__half2*)(o1 + n) = __floats2half2_rn(fmaxf(acc[nt][0] + b0, 0.f), fmaxf(acc[nt][1] + b1, 0.f));
        *(__half2*)(o2 + n) = __floats2half2_rn(fmaxf(acc[nt][2] + b0, 0.f), fmaxf(acc[nt][3] + b1, 0.f));
    }
}

// ---------------- conv3: 64 -> 2 via mma fp16 (N padded to 8) ----------------
__global__ __launch_bounds__(256) void conv3_mma(const float* __restrict__ bias) {
    int x0 = blockIdx.x * 128, y = blockIdx.y, b = blockIdx.z;
    int wid = threadIdx.x >> 5, lane = threadIdx.x & 31;
    int g = lane >> 2, t = lane & 3;
    int m = wid * 16 + g;
    float acc[4] = {0.f, 0.f, 0.f, 0.f};
#pragma unroll
    for (int ky = 0; ky < 3; ky++) {
        int yy = y + ky - 1;
        if ((unsigned)yy >= HH) continue;
        const __half* hrow = g_h2n + ((size_t)(b * HH + yy)) * WW * 64;
#pragma unroll
        for (int kx = 0; kx < 3; kx++) {
            int xb = x0 + kx - 1;
            const __half* wt = g_w3t + (ky * 3 + kx) * 512;
            int x1 = xb + m, x2 = x1 + 8;
            bool ok1 = (unsigned)x1 < WW, ok2 = (unsigned)x2 < WW;
            const __half* p1 = hrow + (size_t)x1 * 64;
            const __half* p2 = hrow + (size_t)x2 * 64;
#pragma unroll
            for (int kk = 0; kk < 4; kk++) {
                int ci = kk * 16 + 2 * t;
                unsigned a0 = ok1 ? *(const unsigned*)(p1 + ci) : 0u;
                unsigned a1 = ok2 ? *(const unsigned*)(p2 + ci) : 0u;
                unsigned a2 = ok1 ? *(const unsigned*)(p1 + ci + 8) : 0u;
                unsigned a3 = ok2 ? *(const unsigned*)(p2 + ci + 8) : 0u;
                const __half* wn = wt + g * 64 + ci;
                unsigned b0 = *(const unsigned*)(wn);
                unsigned b1 = *(const unsigned*)(wn + 8);
                mma_f16(acc, a0, a1, a2, a3, b0, b1);
            }
        }
    }
    if (t == 0) {   // cols 0,1 live here
        int px1 = x0 + m, px2 = px1 + 8;
        float b0 = __ldg(bias + 0), b1 = __ldg(bias + 1);
        int base = y * WW;
        g_tmp2[(b * 2 + 0) * HW + base + px1] = acc[0] + b0;
        g_tmp2[(b * 2 + 1) * HW + base + px1] = acc[1] + b1;
        g_tmp2[(b * 2 + 0) * HW + base + px2] = acc[2] + b0;
        g_tmp2[(b * 2 + 1) * HW + base + px2] = acc[3] + b1;
    }
}

// ---------------- GCN: s^T = (feat @ W1)^T, bf16 [c][b*64+o][m] ----------------
__global__ __launch_bounds__(128) void gcn_s_k(const float* __restrict__ in,
                                               const float* __restrict__ W1) {
    __shared__ float w[36 * 64];
    for (int i = threadIdx.x; i < 2304; i += 128) w[i] = W1[i];
    __syncthreads();
    int idx = blockIdx.x * 128 + threadIdx.x;
    int n = idx & 4095, b = (idx >> 12) & 3, c = idx >> 14;
    int gy = n >> 6, gx = n & 63;
    const float* base = in + (b * 2 + c) * HW + (gy * 6) * WW + gx * 6;
    float f[36];
#pragma unroll
    for (int py = 0; py < 6; py++)
#pragma unroll
        for (int px = 0; px < 6; px++) f[py * 6 + px] = __ldg(base + py * WW + px);
    float acc[64];
#pragma unroll
    for (int o = 0; o < 64; o++) acc[o] = 0.f;
#pragma unroll
    for (int ff = 0; ff < 36; ff++) {
        float fv = f[ff];
        const float* wr = &w[ff * 64];
#pragma unroll
        for (int o = 0; o < 64; o++) acc[o] += fv * wr[o];
    }
    __nv_bfloat16* ob = g_st + (size_t)(c * 256 + b * 64) * NN + n;
#pragma unroll
    for (int o = 0; o < 64; o++) ob[(size_t)o * NN] = __float2bfloat16(acc[o]);
}

// ---------------- GCN: s3^T = (g @ W3)^T, bf16 [c][b*36+o][m] ----------------
__global__ __launch_bounds__(128) void gcn_s3_k(const float* __restrict__ W3) {
    __shared__ float w[64 * 36];
    for (int i = threadIdx.x; i < 2304; i += 128) w[i] = W3[i];
    __syncthreads();
    int idx = blockIdx.x * 128 + threadIdx.x;
    int n = idx & 4095, b = (idx >> 12) & 3, c = idx >> 14;
    const float* gb = g_g + (size_t)(c * NN + n) * 256 + b * 64;
    float acc[36];
#pragma unroll
    for (int o = 0; o < 36; o++) acc[o] = 0.f;
#pragma unroll
    for (int k = 0; k < 64; k++) {
        float gv = gb[k];
        const float* wr = &w[k * 36];
#pragma unroll
        for (int o = 0; o < 36; o++) acc[o] += gv * wr[o];
    }
    __nv_bfloat16* ob = g_s3t + (size_t)(c * 144 + b * 36) * NN + n;
#pragma unroll
    for (int o = 0; o < 36; o++) ob[(size_t)o * NN] = __float2bfloat16(acc[o]);
}

// ---------------- adj GEMM via bf16 mma: C[c] = (relu?)(adj[c] @ B[c]) ----------------
// which 0: B=g_st (Ncols=256), C=g_g, relu.  which 1: B=g_s3t (144), C=g_t3.
// block: 256 thr = 8 warps, tile M=128, N = NT*8. grid (ncol, 32, 2).
template<int NT>
__global__ __launch_bounds__(256) void gemm_mma(int which, int nbase) {
    int c = blockIdx.z;
    const __nv_bfloat16* A = g_adjb + (size_t)c * NN * NN;
    const __nv_bfloat16* Bm; float* C; int Ncols;
    if (which == 0) { Bm = g_st  + (size_t)c * 256 * NN; C = g_g  + (size_t)c * NN * 256; Ncols = 256; }
    else            { Bm = g_s3t + (size_t)c * 144 * NN; C = g_t3 + (size_t)c * NN * 144; Ncols = 144; }
    int n0 = nbase + blockIdx.x * (NT * 8);
    int m0 = blockIdx.y * 128;
    int wid = threadIdx.x >> 5, lane = threadIdx.x & 31;
    int g = lane >> 2, t = lane & 3;
    int r1 = m0 + wid * 16 + g;
    const __nv_bfloat16* ar1 = A + (size_t)r1 * NN;
    const __nv_bfloat16* ar2 = ar1 + (size_t)8 * NN;
    const __nv_bfloat16* br[NT];
#pragma unroll
    for (int nt = 0; nt < NT; nt++) br[nt] = Bm + (size_t)(n0 + nt * 8 + g) * NN;
    float acc[NT][4];
#pragma unroll
    for (int i = 0; i < NT; i++)
#pragma unroll
        for (int j = 0; j < 4; j++) acc[i][j] = 0.f;
#pragma unroll 2
    for (int k0 = 0; k0 < NN; k0 += 16) {
        int kb = k0 + 2 * t;
        unsigned a0 = *(const unsigned*)(ar1 + kb);
        unsigned a1 = *(const unsigned*)(ar2 + kb);
        unsigned a2 = *(const unsigned*)(ar1 + kb + 8);
        unsigned a3 = *(const unsigned*)(ar2 + kb + 8);
#pragma unroll
        for (int nt = 0; nt < NT; nt++) {
            unsigned b0 = *(const unsigned*)(br[nt] + kb);
            unsigned b1 = *(const unsigned*)(br[nt] + kb + 8);
            mma_bf16(acc[nt], a0, a1, a2, a3, b0, b1);
        }
    }
    int r2 = r1 + 8;
#pragma unroll
    for (int nt = 0; nt < NT; nt++) {
        int n = n0 + nt * 8 + 2 * t;
        float v0 = acc[nt][0], v1 = acc[nt][1], v2 = acc[nt][2], v3 = acc[nt][3];
        if (which == 0) { v0 = fmaxf(v0, 0.f); v1 = fmaxf(v1, 0.f); v2 = fmaxf(v2, 0.f); v3 = fmaxf(v3, 0.f); }
        C[(size_t)r1 * Ncols + n] = v0; C[(size_t)r1 * Ncols + n + 1] = v1;
        C[(size_t)r2 * Ncols + n] = v2; C[(size_t)r2 * Ncols + n + 1] = v3;
    }
}

// ---------------- combine: out = in + (1-arf)*tmp2 + arf*tmp3 ----------------
__global__ __launch_bounds__(256) void combine_k(const float* __restrict__ in,
                                                 const float* __restrict__ arf) {
    int g = blockIdx.x * 256 + threadIdx.x;
    int p = g % HW, b = g / HW;
    int x = p % WW, y = p / WW;
    float a = __ldg(arf);
    int gy = y / 6, py = y - gy * 6, gx = x / 6, px = x - gx * 6;
    int n = gy * 64 + gx, f = py * 6 + px;
#pragma unroll
    for (int c = 0; c < 2; c++) {
        float t3v = g_t3[(size_t)(c * NN + n) * 144 + b * 36 + f];
        int li = (b * 2 + c) * HW + p;
        g_oimg[li] = in[li] + (1.f - a) * g_tmp2[li] + a * t3v;
    }
}

// ---------------- z = (-1)^(x+y) * (out_complex * csm) ----------------
__global__ __launch_bounds__(256) void zmake_k(const float* __restrict__ csr,
                                               const float* __restrict__ csi) {
    int idx = blockIdx.x * 256 + threadIdx.x;
    int p = idx % HW, cb = idx / HW;
    int b = cb & 3, c = cb >> 2;
    int x = p % WW, y = p / WW;
    float sgn = ((x + y) & 1) ? -1.f : 1.f;
    float orr = g_oimg[(b * 2 + 0) * HW + p];
    float oii = g_oimg[(b * 2 + 1) * HW + p];
    float cr = __ldg(csr + (size_t)(b * CCH + c) * HW + p);
    float ci = __ldg(csi + (size_t)(b * CCH + c) * HW + p);
    g_k[idx] = make_float2(sgn * (orr * cr - oii * ci), sgn * (orr * ci + oii * cr));
}

__device__ __forceinline__ float2 cadd(float2 a, float2 b) { return make_float2(a.x + b.x, a.y + b.y); }
__device__ __forceinline__ float2 csub(float2 a, float2 b) { return make_float2(a.x - b.x, a.y - b.y); }

// ---------------- row FFT (length 384 = 3 x radix-2-128), in-place ----------------
template<int INV>
__global__ __launch_bounds__(192) void fft_row_k() {
    __shared__ float2 sb[384];
    float2* base = g_k + (size_t)blockIdx.x * 384;
    int tid = threadIdx.x;
    for (int i = tid; i < 384; i += 192) {
        int r = i % 3, q = i / 3;
        sb[r * 128 + q] = base[i];
    }
    __syncthreads();
    int r = tid >> 6, bf = tid & 63, off = r << 7;
#pragma unroll
    for (int len = 128; len >= 2; len >>= 1) {
        int h = len >> 1;
        int grp = bf / h, t = bf - grp * h;
        int i1 = off + grp * len + t;
        float2 u = sb[i1], v = sb[i1 + h];
        sb[i1] = cadd(u, v);
        float2 d = csub(u, v);
        float2 w = g_tw128[t * (128 / len)];
        float wy = INV ? -w.y : w.y;
        sb[i1 + h] = make_float2(d.x * w.x - d.y * wy, d.x * wy + d.y * w.x);
        __syncthreads();
    }
    for (int k = tid; k < 384; k += 192) {
        int k0 = k & 127;
        int rv = __brev((unsigned)k0) >> 25;
        float2 y0 = sb[rv], y1 = sb[128 + rv], y2 = sb[256 + rv];
        float2 c1 = g_tw384[k], c2 = g_tw384[(2 * k) % 384];
        float s1 = INV ? -c1.y : c1.y, s2 = INV ? -c2.y : c2.y;
        float xr = y0.x + c1.x * y1.x - s1 * y1.y + c2.x * y2.x - s2 * y2.y;
        float xi = y0.y + c1.x * y1.y + s1 * y1.x + c2.x * y2.y + s2 * y2.x;
        if (INV) { xr *= (1.f / 384.f); xi *= (1.f / 384.f); }
        base[k] = make_float2(xr, xi);
    }
}

// ---------------- column FFT: 8 columns / block, in-place ----------------
template<int INV>
__global__ __launch_bounds__(192) void fft_col_k() {
    __shared__ float2 sb[8 * 384];
    int img = blockIdx.x / 48, cg = blockIdx.x % 48;
    float2* base = g_k + (size_t)img * HW + cg * 8;
    int tid = threadIdx.x;
    for (int i = tid; i < 3072; i += 192) {
        int col = i & 7, yy = i >> 3;
        int r = yy % 3, q = yy / 3;
        sb[col * 384 + r * 128 + q] = base[(size_t)yy * 384 + col];
    }
    __syncthreads();
#pragma unroll
    for (int len = 128; len >= 2; len >>= 1) {
        int h = len >> 1;
        for (int widx = tid; widx < 1536; widx += 192) {
            int seg = widx >> 6, bf = widx & 63;
            int boff = (seg / 3) * 384 + (seg % 3) * 128;
            int grp = bf / h, t = bf - grp * h;
            int i1 = boff + grp * len + t;
            float2 u = sb[i1], v = sb[i1 + h];
            sb[i1] = cadd(u, v);
            float2 d = csub(u, v);
            float2 w = g_tw128[t * (128 / len)];
            float wy = INV ? -w.y : w.y;
            sb[i1 + h] = make_float2(d.x * w.x - d.y * wy, d.x * wy + d.y * w.x);
        }
        __syncthreads();
    }
    for (int i = tid; i < 3072; i += 192) {
        int col = i & 7, k = i >> 3;
        int k0 = k & 127;
        int rv = __brev((unsigned)k0) >> 25;
        int cb = col * 384;
        float2 y0 = sb[cb + rv], y1 = sb[cb + 128 + rv], y2 = sb[cb + 256 + rv];
        float2 c1 = g_tw384[k], c2 = g_tw384[(2 * k) % 384];
        float s1 = INV ? -c1.y : c1.y, s2 = INV ? -c2.y : c2.y;
        float xr = y0.x + c1.x * y1.x - s1 * y1.y + c2.x * y2.x - s2 * y2.y;
        float xi = y0.y + c1.x * y1.y + s1 * y1.x + c2.x * y2.y + s2 * y2.x;
        if (INV) { xr *= (1.f / 384.f); xi *= (1.f / 384.f); }
        base[(size_t)k * 384 + col] = make_float2(xr, xi);
    }
}

// ---------------- data consistency ----------------
__global__ __launch_bounds__(256) void dc_k(const int* __restrict__ mask,
                                            const float* __restrict__ tkr,
                                            const float* __restrict__ tki) {
    int idx = blockIdx.x * 256 + threadIdx.x;
    int p = idx % HW;
    int x = p % WW, y = p / WW;
    float m = (float)__ldg(mask + p);
    float sgn = ((x + y) & 1) ? -1.f : 1.f;
    float2 Z = g_k[idx];
    float coef = 384.f * 0.999999f * m * sgn;
    float om = 1.f - m;
    g_k[idx] = make_float2(om * Z.x + coef * __ldg(tkr + idx),
                           om * Z.y + coef * __ldg(tki + idx));
}

// ---------------- final coil combine ----------------
__global__ __launch_bounds__(256) void final_k(const float* __restrict__ csr,
                                               const float* __restrict__ csi,
                                               float* __restrict__ out) {
    int g = blockIdx.x * 256 + threadIdx.x;
    int p = g % HW, b = g / HW;
    int x = p % WW, y = p / WW;
    float sgn = ((x + y) & 1) ? -1.f : 1.f;
    float rr = 0.f, ri = 0.f;
#pragma unroll
    for (int c = 0; c < CCH; c++) {
        float2 z = g_k[(size_t)(c * BSZ + b) * HW + p];
        float cr = __ldg(csr + (size_t)(b * CCH + c) * HW + p);
        float ci = __ldg(csi + (size_t)(b * CCH + c) * HW + p);
        rr += z.x * cr + z.y * ci;
        ri += z.y * cr - z.x * ci;
    }
    out[(b * 2 + 0) * HW + p] = sgn * rr;
    out[(b * 2 + 1) * HW + p] = sgn * ri;
}

// ---------------- launch ----------------
extern "C" void kernel_launch(void* const* d_in, const int* in_sizes, int n_in,
                              void* d_out, int out_size) {
    (void)in_sizes; (void)n_in; (void)out_size;
    const float* input = (const float*)d_in[0];
    const float* adj   = (const float*)d_in[1];
    const int*   mask  = (const int*)  d_in[2];
    const float* csr   = (const float*)d_in[3];
    const float* csi   = (const float*)d_in[4];
    const float* tkr   = (const float*)d_in[5];
    const float* tki   = (const float*)d_in[6];
    const float* W1    = (const float*)d_in[7];
    const float* W3    = (const float*)d_in[8];
    const float* arf   = (const float*)d_in[9];
    const float* cw1   = (const float*)d_in[10];
    const float* cb1   = (const float*)d_in[11];
    const float* cw2   = (const float*)d_in[12];
    const float* cb2   = (const float*)d_in[13];
    const float* cw3   = (const float*)d_in[14];
    const float* cb3   = (const float*)d_in[15];
    float* out = (float*)d_out;

    init_tw_k<<<1, 384>>>();
    prep_w_k<<<144, 256>>>(cw2, cw3);
    adj_cvt_k<<<32768, 256>>>(adj);

    // CNN branch
    conv1_k<<<2304, 256>>>(input, cw1, cb1);
    conv2_mma<<<dim3(3, 384, 4), 256>>>(cb2);
    conv3_mma<<<dim3(3, 384, 4), 256>>>(cb3);

    // GCN branch
    gcn_s_k<<<256, 128>>>(input, W1);
    gemm_mma<8><<<dim3(4, 32, 2), 256>>>(0, 0);     // g = relu(adj @ s), N=256
    gcn_s3_k<<<256, 128>>>(W3);
    gemm_mma<8><<<dim3(2, 32, 2), 256>>>(1, 0);     // t3 cols 0..127
    gemm_mma<2><<<dim3(1, 32, 2), 256>>>(1, 128);   // t3 cols 128..143

    // combine + data consistency
    combine_k<<<2304, 256>>>(input, arf);
    zmake_k<<<27648, 256>>>(csr, csi);
    fft_row_k<0><<<48 * 384, 192>>>();
    fft_col_k<0><<<48 * 48, 192>>>();
    dc_k<<<27648, 256>>>(mask, tkr, tki);
    fft_col_k<1><<<48 * 48, 192>>>();
    fft_row_k<1><<<48 * 384, 192>>>();
    final_k<<<2304, 256>>>(csr, csi, out);
}

// round 6
// speedup vs baseline: 2.0294x; 1.2637x over previous
#include <cuda_runtime.h>
#include <cuda_fp16.h>
#include <cuda_bf16.h>
#include <math.h>
#include <stdint.h>
#include <stddef.h>

#define BSZ 4
#define CCH 12
#define HH 384
#define WW 384
#define HW (HH*WW)
#define NN 4096

// ---------------- static device scratch (no allocs allowed) ----------------
__device__ __half         g_h1n[(size_t)BSZ*HW*64];   // conv1 out, NHWC fp16
__device__ __half         g_h2n[(size_t)BSZ*HW*64];   // conv2 out, NHWC fp16
__device__ __nv_bfloat16  g_adjb[(size_t)2*NN*NN];    // adj bf16
__device__ __half         g_w2t[9*64*64];             // conv2 w [tap][co][ci]
__device__ __half         g_w3t[9*8*64];              // conv3 w [tap][o pad8][ci]
__device__ __nv_bfloat16  g_st [(size_t)2*256*NN];    // s^T  [c][b*64+o][m]
__device__ __nv_bfloat16  g_s3t[(size_t)2*144*NN];    // s3^T [c][b*36+o][m]
__device__ float          g_g  [(size_t)2*NN*256];    // relu(adj@s) [c][m][256]
__device__ float          g_t3 [(size_t)2*NN*144];    // adj@s3 [c][m][144]
__device__ float          g_tmp2[BSZ*2*HW];
__device__ float          g_oimg[BSZ*2*HW];
__device__ float2         g_k[(size_t)CCH*BSZ*HW];
__device__ float2         g_tw128[64];
__device__ float2         g_tw384[384];

// ---------------- mma wrappers (m16n8k16, f32 accum) ----------------
__device__ __forceinline__ void mma_f16(float c[4], unsigned a0, unsigned a1,
                                        unsigned a2, unsigned a3,
                                        unsigned b0, unsigned b1) {
    asm volatile("mma.sync.aligned.m16n8k16.row.col.f32.f16.f16.f32 "
        "{%0,%1,%2,%3}, {%4,%5,%6,%7}, {%8,%9}, {%0,%1,%2,%3};"
        : "+f"(c[0]), "+f"(c[1]), "+f"(c[2]), "+f"(c[3])
        : "r"(a0), "r"(a1), "r"(a2), "r"(a3), "r"(b0), "r"(b1));
}
__device__ __forceinline__ void mma_bf16(float c[4], unsigned a0, unsigned a1,
                                         unsigned a2, unsigned a3,
                                         unsigned b0, unsigned b1) {
    asm volatile("mma.sync.aligned.m16n8k16.row.col.f32.bf16.bf16.f32 "
        "{%0,%1,%2,%3}, {%4,%5,%6,%7}, {%8,%9}, {%0,%1,%2,%3};"
        : "+f"(c[0]), "+f"(c[1]), "+f"(c[2]), "+f"(c[3])
        : "r"(a0), "r"(a1), "r"(a2), "r"(a3), "r"(b0), "r"(b1));
}

// ---------------- init ----------------
__global__ void init_tw_k() {
    int t = threadIdx.x;
    if (t < 64) { float s, c; sincospif(-(float)t / 64.f, &s, &c);  g_tw128[t] = make_float2(c, s); }
    {            float s, c; sincospif(-(float)t / 192.f, &s, &c); g_tw384[t] = make_float2(c, s); }
}
__global__ void prep_w_k(const float* __restrict__ cw2, const float* __restrict__ cw3) {
    int i = blockIdx.x * 256 + threadIdx.x;
    if (i < 9 * 64 * 64) {
        int tap = i / 4096, r = i % 4096, co = r >> 6, ci = r & 63;
        g_w2t[i] = __float2half(cw2[(co * 64 + ci) * 9 + tap]);
    }
    if (i < 9 * 8 * 64) {
        int tap = i / 512, r = i % 512, o = r >> 6, ci = r & 63;
        g_w3t[i] = __float2half((o < 2) ? cw3[(o * 64 + ci) * 9 + tap] : 0.f);
    }
}
__global__ __launch_bounds__(256) void adj_cvt_k(const float* __restrict__ adj) {
    size_t i = ((size_t)blockIdx.x * 256 + threadIdx.x) * 4;
    float4 v = *(const float4*)(adj + i);
    __nv_bfloat162* o = (__nv_bfloat162*)(g_adjb + i);
    o[0] = __floats2bfloat162_rn(v.x, v.y);
    o[1] = __floats2bfloat162_rn(v.z, v.w);
}

// ---------------- conv1: 2 -> 64, relu, NHWC fp16; 2 thr/pixel x 32 ch ----------------
__global__ __launch_bounds__(256) void conv1_k(const float* __restrict__ in,
                                               const float* __restrict__ w,
                                               const float* __restrict__ bias) {
    __shared__ float ws[18 * 64];   // [q=ci*9+tap][co]
    for (int i = threadIdx.x; i < 1152; i += 256) {
        int co = i / 18, q = i % 18;
        ws[q * 64 + co] = w[i];
    }
    __syncthreads();
    int tid = threadIdx.x;
    int p = blockIdx.x * 128 + (tid >> 1);
    int half = tid & 1;                    // channel half: [half*32, half*32+32)
    int x = p % WW, y = (p / WW) % HH, b = p / HW;
    float acc[32];
#pragma unroll
    for (int co = 0; co < 32; co++) acc[co] = __ldg(bias + half * 32 + co);
    for (int ci = 0; ci < 2; ci++) {
        const float* base = in + (b * 2 + ci) * HW;
#pragma unroll
        for (int ky = 0; ky < 3; ky++) {
            int yy = y + ky - 1; bool yok = (unsigned)yy < HH;
#pragma unroll
            for (int kx = 0; kx < 3; kx++) {
                int xx = x + kx - 1;
                float v = (yok && (unsigned)xx < WW) ? __ldg(base + yy * WW + xx) : 0.f;
                const float* wr = &ws[(ci * 9 + ky * 3 + kx) * 64 + half * 32];
#pragma unroll
                for (int co = 0; co < 32; co++) acc[co] += v * wr[co];
            }
        }
    }
    __half2 h2[16];
#pragma unroll
    for (int co = 0; co < 32; co += 2)
        h2[co >> 1] = __floats2half2_rn(fmaxf(acc[co], 0.f), fmaxf(acc[co + 1], 0.f));
    uint4* ob = (uint4*)(g_h1n + (size_t)p * 64 + half * 32);
    const uint4* src = (const uint4*)h2;
#pragma unroll
    for (int i = 0; i < 4; i++) ob[i] = src[i];
}

// ---------------- conv2: 64 -> 64 via mma fp16, relu; M=32/warp (2 rows) ----------------
// grid (6, 192, 4), 128 thr = 4 warps; x strip 64, y pair
__global__ __launch_bounds__(128) void conv2_mma(const float* __restrict__ bias) {
    int x0 = blockIdx.x * 64, y0 = blockIdx.y * 2, b = blockIdx.z;
    int wid = threadIdx.x >> 5, lane = threadIdx.x & 31;
    int g = lane >> 2, t = lane & 3;
    int m = wid * 16 + g;
    float acc[2][8][4];
#pragma unroll
    for (int r = 0; r < 2; r++)
#pragma unroll
        for (int i = 0; i < 8; i++)
#pragma unroll
            for (int j = 0; j < 4; j++) acc[r][i][j] = 0.f;
#pragma unroll
    for (int ky = 0; ky < 3; ky++) {
        int ya = y0 + ky - 1, yb = ya + 1;
        bool oka = (unsigned)ya < HH, okb = (unsigned)yb < HH;
        const __half* rowa = g_h1n + (ptrdiff_t)(b * HH + ya) * (WW * 64);
        const __half* rowb = rowa + WW * 64;
#pragma unroll
        for (int kx = 0; kx < 3; kx++) {
            int x1 = x0 + kx - 1 + m, x2 = x1 + 8;
            bool ok1 = (unsigned)x1 < WW, ok2 = (unsigned)x2 < WW;
            const __half* wt = g_w2t + (ky * 3 + kx) * 4096;
            const __half* pa1 = rowa + (ptrdiff_t)x1 * 64;
            const __half* pa2 = rowa + (ptrdiff_t)x2 * 64;
            const __half* pb1 = rowb + (ptrdiff_t)x1 * 64;
            const __half* pb2 = rowb + (ptrdiff_t)x2 * 64;
#pragma unroll
            for (int kk = 0; kk < 4; kk++) {
                int ci = kk * 16 + 2 * t;
                unsigned A0 = (oka && ok1) ? *(const unsigned*)(pa1 + ci) : 0u;
                unsigned A1 = (oka && ok2) ? *(const unsigned*)(pa2 + ci) : 0u;
                unsigned A2 = (oka && ok1) ? *(const unsigned*)(pa1 + ci + 8) : 0u;
                unsigned A3 = (oka && ok2) ? *(const unsigned*)(pa2 + ci + 8) : 0u;
                unsigned C0 = (okb && ok1) ? *(const unsigned*)(pb1 + ci) : 0u;
                unsigned C1 = (okb && ok2) ? *(const unsigned*)(pb2 + ci) : 0u;
                unsigned C2 = (okb && ok1) ? *(const unsigned*)(pb1 + ci + 8) : 0u;
                unsigned C3 = (okb && ok2) ? *(const unsigned*)(pb2 + ci + 8) : 0u;
#pragma unroll
                for (int nt = 0; nt < 8; nt++) {
                    const __half* wn = wt + (nt * 8 + g) * 64 + ci;
                    unsigned w0 = *(const unsigned*)(wn);
                    unsigned w1 = *(const unsigned*)(wn + 8);
                    mma_f16(acc[0][nt], A0, A1, A2, A3, w0, w1);
                    mma_f16(acc[1][nt], C0, C1, C2, C3, w0, w1);
                }
            }
        }
    }
    int px1 = x0 + m;
#pragma unroll
    for (int r = 0; r < 2; r++) {
        int y = y0 + r;
        __half* o1 = g_h2n + ((size_t)(b * HH + y) * WW + px1) * 64;
        __half* o2 = o1 + 8 * 64;
#pragma unroll
        for (int nt = 0; nt < 8; nt++) {
            int n = nt * 8 + 2 * t;
            float b0 = __ldg(bias + n), b1 = __ldg(bias + n + 1);
            *(__half2*)(o1 + n) = __floats2half2_rn(fmaxf(acc[r][nt][0] + b0, 0.f), fmaxf(acc[r][nt][1] + b1, 0.f));
            *(__half2*)(o2 + n) = __floats2half2_rn(fmaxf(acc[r][nt][2] + b0, 0.f), fmaxf(acc[r][nt][3] + b1, 0.f));
        }
    }
}

// ---------------- conv3: 64 -> 2 via mma fp16 (N padded to 8) ----------------
__global__ __launch_bounds__(256) void conv3_mma(const float* __restrict__ bias) {
    int x0 = blockIdx.x * 128, y = blockIdx.y, b = blockIdx.z;
    int wid = threadIdx.x >> 5, lane = threadIdx.x & 31;
    int g = lane >> 2, t = lane & 3;
    int m = wid * 16 + g;
    float acc[4] = {0.f, 0.f, 0.f, 0.f};
#pragma unroll
    for (int ky = 0; ky < 3; ky++) {
        int yy = y + ky - 1;
        if ((unsigned)yy >= HH) continue;
        const __half* hrow = g_h2n + ((size_t)(b * HH + yy)) * WW * 64;
#pragma unroll
        for (int kx = 0; kx < 3; kx++) {
            int xb = x0 + kx - 1;
            const __half* wt = g_w3t + (ky * 3 + kx) * 512;
            int x1 = xb + m, x2 = x1 + 8;
            bool ok1 = (unsigned)x1 < WW, ok2 = (unsigned)x2 < WW;
            const __half* p1 = hrow + (ptrdiff_t)x1 * 64;
            const __half* p2 = hrow + (ptrdiff_t)x2 * 64;
#pragma unroll
            for (int kk = 0; kk < 4; kk++) {
                int ci = kk * 16 + 2 * t;
                unsigned a0 = ok1 ? *(const unsigned*)(p1 + ci) : 0u;
                unsigned a1 = ok2 ? *(const unsigned*)(p2 + ci) : 0u;
                unsigned a2 = ok1 ? *(const unsigned*)(p1 + ci + 8) : 0u;
                unsigned a3 = ok2 ? *(const unsigned*)(p2 + ci + 8) : 0u;
                const __half* wn = wt + g * 64 + ci;
                unsigned b0 = *(const unsigned*)(wn);
                unsigned b1 = *(const unsigned*)(wn + 8);
                mma_f16(acc, a0, a1, a2, a3, b0, b1);
            }
        }
    }
    if (t == 0) {
        int px1 = x0 + m, px2 = px1 + 8;
        float b0 = __ldg(bias + 0), b1 = __ldg(bias + 1);
        int base = y * WW;
        g_tmp2[(b * 2 + 0) * HW + base + px1] = acc[0] + b0;
        g_tmp2[(b * 2 + 1) * HW + base + px1] = acc[1] + b1;
        g_tmp2[(b * 2 + 0) * HW + base + px2] = acc[2] + b0;
        g_tmp2[(b * 2 + 1) * HW + base + px2] = acc[3] + b1;
    }
}

// ---------------- GCN: s^T = (feat @ W1)^T, bf16 ----------------
__global__ __launch_bounds__(128) void gcn_s_k(const float* __restrict__ in,
                                               const float* __restrict__ W1) {
    __shared__ float w[36 * 64];
    for (int i = threadIdx.x; i < 2304; i += 128) w[i] = W1[i];
    __syncthreads();
    int idx = blockIdx.x * 128 + threadIdx.x;
    int n = idx & 4095, b = (idx >> 12) & 3, c = idx >> 14;
    int gy = n >> 6, gx = n & 63;
    const float* base = in + (b * 2 + c) * HW + (gy * 6) * WW + gx * 6;
    float f[36];
#pragma unroll
    for (int py = 0; py < 6; py++)
#pragma unroll
        for (int px = 0; px < 6; px++) f[py * 6 + px] = __ldg(base + py * WW + px);
    float acc[64];
#pragma unroll
    for (int o = 0; o < 64; o++) acc[o] = 0.f;
#pragma unroll
    for (int ff = 0; ff < 36; ff++) {
        float fv = f[ff];
        const float* wr = &w[ff * 64];
#pragma unroll
        for (int o = 0; o < 64; o++) acc[o] += fv * wr[o];
    }
    __nv_bfloat16* ob = g_st + (size_t)(c * 256 + b * 64) * NN + n;
#pragma unroll
    for (int o = 0; o < 64; o++) ob[(size_t)o * NN] = __float2bfloat16(acc[o]);
}

// ---------------- GCN: s3^T = (g @ W3)^T, bf16 ----------------
__global__ __launch_bounds__(128) void gcn_s3_k(const float* __restrict__ W3) {
    __shared__ float w[64 * 36];
    for (int i = threadIdx.x; i < 2304; i += 128) w[i] = W3[i];
    __syncthreads();
    int idx = blockIdx.x * 128 + threadIdx.x;
    int n = idx & 4095, b = (idx >> 12) & 3, c = idx >> 14;
    const float* gb = g_g + (size_t)(c * NN + n) * 256 + b * 64;
    float acc[36];
#pragma unroll
    for (int o = 0; o < 36; o++) acc[o] = 0.f;
#pragma unroll
    for (int k = 0; k < 64; k++) {
        float gv = gb[k];
        const float* wr = &w[k * 36];
#pragma unroll
        for (int o = 0; o < 36; o++) acc[o] += gv * wr[o];
    }
    __nv_bfloat16* ob = g_s3t + (size_t)(c * 144 + b * 36) * NN + n;
#pragma unroll
    for (int o = 0; o < 36; o++) ob[(size_t)o * NN] = __float2bfloat16(acc[o]);
}

// ---------------- adj GEMM via bf16 mma, M=32/warp ----------------
// block 128 thr = 4 warps x 32 rows = 128 rows; grid (ncol, 32, 2)
template<int NT>
__global__ __launch_bounds__(128) void gemm_mma(int which, int nbase) {
    int c = blockIdx.z;
    const __nv_bfloat16* A = g_adjb + (size_t)c * NN * NN;
    const __nv_bfloat16* Bm; float* C; int Ncols;
    if (which == 0) { Bm = g_st  + (size_t)c * 256 * NN; C = g_g  + (size_t)c * NN * 256; Ncols = 256; }
    else            { Bm = g_s3t + (size_t)c * 144 * NN; C = g_t3 + (size_t)c * NN * 144; Ncols = 144; }
    int n0 = nbase + blockIdx.x * (NT * 8);
    int m0 = blockIdx.y * 128;
    int wid = threadIdx.x >> 5, lane = threadIdx.x & 31;
    int g = lane >> 2, t = lane & 3;
    int r1 = m0 + wid * 32 + g;
    const __nv_bfloat16* ar0 = A + (size_t)r1 * NN;
    const __nv_bfloat16* ar1 = ar0 + (size_t)8 * NN;
    const __nv_bfloat16* ar2 = ar0 + (size_t)16 * NN;
    const __nv_bfloat16* ar3 = ar0 + (size_t)24 * NN;
    const __nv_bfloat16* br[NT];
#pragma unroll
    for (int nt = 0; nt < NT; nt++) br[nt] = Bm + (size_t)(n0 + nt * 8 + g) * NN;
    float acc[2][NT][4];
#pragma unroll
    for (int r = 0; r < 2; r++)
#pragma unroll
        for (int i = 0; i < NT; i++)
#pragma unroll
            for (int j = 0; j < 4; j++) acc[r][i][j] = 0.f;
#pragma unroll 2
    for (int k0 = 0; k0 < NN; k0 += 16) {
        int kb = k0 + 2 * t;
        unsigned a0 = *(const unsigned*)(ar0 + kb);
        unsigned a1 = *(const unsigned*)(ar1 + kb);
        unsigned a2 = *(const unsigned*)(ar0 + kb + 8);
        unsigned a3 = *(const unsigned*)(ar1 + kb + 8);
        unsigned c0 = *(const unsigned*)(ar2 + kb);
        unsigned c1 = *(const unsigned*)(ar3 + kb);
        unsigned c2 = *(const unsigned*)(ar2 + kb + 8);
        unsigned c3 = *(const unsigned*)(ar3 + kb + 8);
#pragma unroll
        for (int nt = 0; nt < NT; nt++) {
            unsigned b0 = *(const unsigned*)(br[nt] + kb);
            unsigned b1 = *(const unsigned*)(br[nt] + kb + 8);
            mma_bf16(acc[0][nt], a0, a1, a2, a3, b0, b1);
            mma_bf16(acc[1][nt], c0, c1, c2, c3, b0, b1);
        }
    }
#pragma unroll
    for (int r = 0; r < 2; r++) {
        int ra = r1 + r * 16, rb = ra + 8;
#pragma unroll
        for (int nt = 0; nt < NT; nt++) {
            int n = n0 + nt * 8 + 2 * t;
            float v0 = acc[r][nt][0], v1 = acc[r][nt][1], v2 = acc[r][nt][2], v3 = acc[r][nt][3];
            if (which == 0) { v0 = fmaxf(v0, 0.f); v1 = fmaxf(v1, 0.f); v2 = fmaxf(v2, 0.f); v3 = fmaxf(v3, 0.f); }
            C[(size_t)ra * Ncols + n] = v0; C[(size_t)ra * Ncols + n + 1] = v1;
            C[(size_t)rb * Ncols + n] = v2; C[(size_t)rb * Ncols + n + 1] = v3;
        }
    }
}

// ---------------- combine: out = in + (1-arf)*tmp2 + arf*tmp3 ----------------
__global__ __launch_bounds__(256) void combine_k(const float* __restrict__ in,
                                                 const float* __restrict__ arf) {
    int g = blockIdx.x * 256 + threadIdx.x;
    int p = g % HW, b = g / HW;
    int x = p % WW, y = p / WW;
    float a = __ldg(arf);
    int gy = y / 6, py = y - gy * 6, gx = x / 6, px = x - gx * 6;
    int n = gy * 64 + gx, f = py * 6 + px;
#pragma unroll
    for (int c = 0; c < 2; c++) {
        float t3v = g_t3[(size_t)(c * NN + n) * 144 + b * 36 + f];
        int li = (b * 2 + c) * HW + p;
        g_oimg[li] = in[li] + (1.f - a) * g_tmp2[li] + a * t3v;
    }
}

__device__ __forceinline__ float2 cadd(float2 a, float2 b) { return make_float2(a.x + b.x, a.y + b.y); }
__device__ __forceinline__ float2 csub(float2 a, float2 b) { return make_float2(a.x - b.x, a.y - b.y); }

// ---------------- row FFT; FUSED=1: compute z=(-1)^(x+y)*oimg*csm at load ----------------
template<int INV, int FUSED>
__global__ __launch_bounds__(192) void fft_row_k(const float* __restrict__ csr,
                                                 const float* __restrict__ csi) {
    __shared__ float2 sb[384];
    int line = blockIdx.x;                 // img*384 + y
    float2* base = g_k + (size_t)line * 384;
    int tid = threadIdx.x;
    if (FUSED) {
        int img = line / HH, y = line % HH;
        int b = img & 3, c = img >> 2;
        const float* o0 = g_oimg + (size_t)(b * 2 + 0) * HW + y * WW;
        const float* o1 = g_oimg + (size_t)(b * 2 + 1) * HW + y * WW;
        const float* cr = csr + (size_t)(b * CCH + c) * HW + y * WW;
        const float* ci = csi + (size_t)(b * CCH + c) * HW + y * WW;
        for (int i = tid; i < 384; i += 192) {
            float orr = o0[i], oii = o1[i];
            float crv = __ldg(cr + i), civ = __ldg(ci + i);
            float sgn = ((i + y) & 1) ? -1.f : 1.f;
            float2 z = make_float2(sgn * (orr * crv - oii * civ), sgn * (orr * civ + oii * crv));
            int r = i % 3, q = i / 3;
            sb[r * 128 + q] = z;
        }
    } else {
        for (int i = tid; i < 384; i += 192) {
            int r = i % 3, q = i / 3;
            sb[r * 128 + q] = base[i];
        }
    }
    __syncthreads();
    int r = tid >> 6, bf = tid & 63, off = r << 7;
#pragma unroll
    for (int len = 128; len >= 2; len >>= 1) {
        int h = len >> 1;
        int grp = bf / h, t = bf - grp * h;
        int i1 = off + grp * len + t;
        float2 u = sb[i1], v = sb[i1 + h];
        sb[i1] = cadd(u, v);
        float2 d = csub(u, v);
        float2 w = g_tw128[t * (128 / len)];
        float wy = INV ? -w.y : w.y;
        sb[i1 + h] = make_float2(d.x * w.x - d.y * wy, d.x * wy + d.y * w.x);
        __syncthreads();
    }
    for (int k = tid; k < 384; k += 192) {
        int k0 = k & 127;
        int rv = __brev((unsigned)k0) >> 25;
        float2 y0 = sb[rv], y1 = sb[128 + rv], y2 = sb[256 + rv];
        float2 c1 = g_tw384[k], c2 = g_tw384[(2 * k) % 384];
        float s1 = INV ? -c1.y : c1.y, s2 = INV ? -c2.y : c2.y;
        float xr = y0.x + c1.x * y1.x - s1 * y1.y + c2.x * y2.x - s2 * y2.y;
        float xi = y0.y + c1.x * y1.y + s1 * y1.x + c2.x * y2.y + s2 * y2.x;
        if (INV) { xr *= (1.f / 384.f); xi *= (1.f / 384.f); }
        base[k] = make_float2(xr, xi);
    }
}

// ---------------- column FFT; DC=1: apply data consistency at load ----------------
template<int INV, int DC>
__global__ __launch_bounds__(192) void fft_col_k(const int* __restrict__ mask,
                                                 const float* __restrict__ tkr,
                                                 const float* __restrict__ tki) {
    __shared__ float2 sb[8 * 384];
    int img = blockIdx.x / 48, cg = blockIdx.x % 48;
    float2* base = g_k + (size_t)img * HW + cg * 8;
    int tid = threadIdx.x;
    for (int i = tid; i < 3072; i += 192) {
        int col = i & 7, yy = i >> 3;
        float2 Z = base[(size_t)yy * 384 + col];
        if (DC) {
            int gx = cg * 8 + col;
            int p = yy * 384 + gx;
            float mv = (float)__ldg(mask + p);
            float sgn = ((gx + yy) & 1) ? -1.f : 1.f;
            float coef = 384.f * 0.999999f * mv * sgn;
            float om = 1.f - mv;
            size_t gidx = (size_t)img * HW + p;
            Z.x = om * Z.x + coef * __ldg(tkr + gidx);
            Z.y = om * Z.y + coef * __ldg(tki + gidx);
        }
        int r = yy % 3, q = yy / 3;
        sb[col * 384 + r * 128 + q] = Z;
    }
    __syncthreads();
#pragma unroll
    for (int len = 128; len >= 2; len >>= 1) {
        int h = len >> 1;
        for (int widx = tid; widx < 1536; widx += 192) {
            int seg = widx >> 6, bf = widx & 63;
            int boff = (seg / 3) * 384 + (seg % 3) * 128;
            int grp = bf / h, t = bf - grp * h;
            int i1 = boff + grp * len + t;
            float2 u = sb[i1], v = sb[i1 + h];
            sb[i1] = cadd(u, v);
            float2 d = csub(u, v);
            float2 w = g_tw128[t * (128 / len)];
            float wy = INV ? -w.y : w.y;
            sb[i1 + h] = make_float2(d.x * w.x - d.y * wy, d.x * wy + d.y * w.x);
        }
        __syncthreads();
    }
    for (int i = tid; i < 3072; i += 192) {
        int col = i & 7, k = i >> 3;
        int k0 = k & 127;
        int rv = __brev((unsigned)k0) >> 25;
        int cb = col * 384;
        float2 y0 = sb[cb + rv], y1 = sb[cb + 128 + rv], y2 = sb[cb + 256 + rv];
        float2 c1 = g_tw384[k], c2 = g_tw384[(2 * k) % 384];
        float s1 = INV ? -c1.y : c1.y, s2 = INV ? -c2.y : c2.y;
        float xr = y0.x + c1.x * y1.x - s1 * y1.y + c2.x * y2.x - s2 * y2.y;
        float xi = y0.y + c1.x * y1.y + s1 * y1.x + c2.x * y2.y + s2 * y2.x;
        if (INV) { xr *= (1.f / 384.f); xi *= (1.f / 384.f); }
        base[(size_t)k * 384 + col] = make_float2(xr, xi);
    }
}

// ---------------- final coil combine ----------------
__global__ __launch_bounds__(256) void final_k(const float* __restrict__ csr,
                                               const float* __restrict__ csi,
                                               float* __restrict__ out) {
    int g = blockIdx.x * 256 + threadIdx.x;
    int p = g % HW, b = g / HW;
    int x = p % WW, y = p / WW;
    float sgn = ((x + y) & 1) ? -1.f : 1.f;
    float rr = 0.f, ri = 0.f;
#pragma unroll
    for (int c = 0; c < CCH; c++) {
        float2 z = g_k[(size_t)(c * BSZ + b) * HW + p];
        float cr = __ldg(csr + (size_t)(b * CCH + c) * HW + p);
        float ci = __ldg(csi + (size_t)(b * CCH + c) * HW + p);
        rr += z.x * cr + z.y * ci;
        ri += z.y * cr - z.x * ci;
    }
    out[(b * 2 + 0) * HW + p] = sgn * rr;
    out[(b * 2 + 1) * HW + p] = sgn * ri;
}

// ---------------- launch ----------------
extern "C" void kernel_launch(void* const* d_in, const int* in_sizes, int n_in,
                              void* d_out, int out_size) {
    (void)in_sizes; (void)n_in; (void)out_size;
    const float* input = (const float*)d_in[0];
    const float* adj   = (const float*)d_in[1];
    const int*   mask  = (const int*)  d_in[2];
    const float* csr   = (const float*)d_in[3];
    const float* csi   = (const float*)d_in[4];
    const float* tkr   = (const float*)d_in[5];
    const float* tki   = (const float*)d_in[6];
    const float* W1    = (const float*)d_in[7];
    const float* W3    = (const float*)d_in[8];
    const float* arf   = (const float*)d_in[9];
    const float* cw1   = (const float*)d_in[10];
    const float* cb1   = (const float*)d_in[11];
    const float* cw2   = (const float*)d_in[12];
    const float* cb2   = (const float*)d_in[13];
    const float* cw3   = (const float*)d_in[14];
    const float* cb3   = (const float*)d_in[15];
    float* out = (float*)d_out;

    init_tw_k<<<1, 384>>>();
    prep_w_k<<<144, 256>>>(cw2, cw3);
    adj_cvt_k<<<32768, 256>>>(adj);

    // CNN branch
    conv1_k<<<4608, 256>>>(input, cw1, cb1);
    conv2_mma<<<dim3(6, 192, 4), 128>>>(cb2);
    conv3_mma<<<dim3(3, 384, 4), 256>>>(cb3);

    // GCN branch
    gcn_s_k<<<256, 128>>>(input, W1);
    gemm_mma<8><<<dim3(4, 32, 2), 128>>>(0, 0);     // g = relu(adj @ s), N=256
    gcn_s3_k<<<256, 128>>>(W3);
    gemm_mma<8><<<dim3(2, 32, 2), 128>>>(1, 0);     // t3 cols 0..127
    gemm_mma<2><<<dim3(1, 32, 2), 128>>>(1, 128);   // t3 cols 128..143

    // combine + FFT chain (zmake fused into fwd row FFT, dc fused into inv col FFT)
    combine_k<<<2304, 256>>>(input, arf);
    fft_row_k<0, 1><<<48 * 384, 192>>>(csr, csi);
    fft_col_k<0, 0><<<48 * 48, 192>>>(nullptr, nullptr, nullptr);
    fft_col_k<1, 1><<<48 * 48, 192>>>(mask, tkr, tki);
    fft_row_k<1, 0><<<48 * 384, 192>>>(nullptr, nullptr);
    final_k<<<2304, 256>>>(csr, csi, out);
}

// round 7
// speedup vs baseline: 2.2199x; 1.0939x over previous
#include <cuda_runtime.h>
#include <cuda_fp16.h>
#include <cuda_bf16.h>
#include <math.h>
#include <stdint.h>
#include <stddef.h>

#define BSZ 4
#define CCH 12
#define HH 384
#define WW 384
#define HW (HH*WW)
#define NN 4096

// ---------------- static device scratch (no allocs allowed) ----------------
__device__ __half         g_h1n[(size_t)BSZ*HW*64];   // conv1 out, NHWC fp16
__device__ __half         g_h2n[(size_t)BSZ*HW*64];   // conv2 out, NHWC fp16
__device__ __nv_bfloat16  g_adjb[(size_t)2*NN*NN];    // adj bf16
__device__ __half         g_w2t[9*64*64];             // conv2 w [tap][co][ci]
__device__ __half         g_w3t[9*8*64];              // conv3 w [tap][o pad8][ci]
__device__ __nv_bfloat16  g_st [(size_t)2*256*NN];    // s^T  [c][b*64+o][m]
__device__ __nv_bfloat16  g_s3t[(size_t)2*144*NN];    // s3^T [c][b*36+o][m]
__device__ float          g_g  [(size_t)2*NN*256];    // relu(adj@s) [c][m][256]
__device__ float          g_t3 [(size_t)2*NN*144];    // adj@s3 [c][m][144]
__device__ float          g_tmp2[BSZ*2*HW];
__device__ float          g_oimg[BSZ*2*HW];
__device__ float2         g_k[(size_t)CCH*BSZ*HW];
__device__ float2         g_tw128[64];
__device__ float2         g_tw384[384];

// ---------------- mma wrappers (m16n8k16, f32 accum) ----------------
__device__ __forceinline__ void mma_f16(float c[4], unsigned a0, unsigned a1,
                                        unsigned a2, unsigned a3,
                                        unsigned b0, unsigned b1) {
    asm volatile("mma.sync.aligned.m16n8k16.row.col.f32.f16.f16.f32 "
        "{%0,%1,%2,%3}, {%4,%5,%6,%7}, {%8,%9}, {%0,%1,%2,%3};"
        : "+f"(c[0]), "+f"(c[1]), "+f"(c[2]), "+f"(c[3])
        : "r"(a0), "r"(a1), "r"(a2), "r"(a3), "r"(b0), "r"(b1));
}
__device__ __forceinline__ void mma_bf16(float c[4], unsigned a0, unsigned a1,
                                         unsigned a2, unsigned a3,
                                         unsigned b0, unsigned b1) {
    asm volatile("mma.sync.aligned.m16n8k16.row.col.f32.bf16.bf16.f32 "
        "{%0,%1,%2,%3}, {%4,%5,%6,%7}, {%8,%9}, {%0,%1,%2,%3};"
        : "+f"(c[0]), "+f"(c[1]), "+f"(c[2]), "+f"(c[3])
        : "r"(a0), "r"(a1), "r"(a2), "r"(a3), "r"(b0), "r"(b1));
}

// ---------------- init ----------------
__global__ void init_tw_k() {
    int t = threadIdx.x;
    if (t < 64) { float s, c; sincospif(-(float)t / 64.f, &s, &c);  g_tw128[t] = make_float2(c, s); }
    {            float s, c; sincospif(-(float)t / 192.f, &s, &c); g_tw384[t] = make_float2(c, s); }
}
__global__ void prep_w_k(const float* __restrict__ cw2, const float* __restrict__ cw3) {
    int i = blockIdx.x * 256 + threadIdx.x;
    if (i < 9 * 64 * 64) {
        int tap = i / 4096, r = i % 4096, co = r >> 6, ci = r & 63;
        g_w2t[i] = __float2half(cw2[(co * 64 + ci) * 9 + tap]);
    }
    if (i < 9 * 8 * 64) {
        int tap = i / 512, r = i % 512, o = r >> 6, ci = r & 63;
        g_w3t[i] = __float2half((o < 2) ? cw3[(o * 64 + ci) * 9 + tap] : 0.f);
    }
}
__global__ __launch_bounds__(256) void adj_cvt_k(const float* __restrict__ adj) {
    size_t i = ((size_t)blockIdx.x * 256 + threadIdx.x) * 4;
    float4 v = *(const float4*)(adj + i);
    __nv_bfloat162* o = (__nv_bfloat162*)(g_adjb + i);
    o[0] = __floats2bfloat162_rn(v.x, v.y);
    o[1] = __floats2bfloat162_rn(v.z, v.w);
}

// ---------------- conv1: 2 -> 64, relu; 4 px x 8 ch per thread ----------------
// grid 4608 (3 chunks/row * 1536 rows), block 256
__global__ __launch_bounds__(256) void conv1_k(const float* __restrict__ in,
                                               const float* __restrict__ w,
                                               const float* __restrict__ bias) {
    __shared__ float ws[18 * 64];   // [q=ci*9+tap][co]
    for (int i = threadIdx.x; i < 1152; i += 256) {
        int co = i / 18, q = i % 18;
        ws[q * 64 + co] = w[i];
    }
    __syncthreads();
    int tid = threadIdx.x;
    int cog = tid & 7;               // 8 channel groups of 8
    int pq  = tid >> 3;              // 32 pixel-quads
    int chunk = blockIdx.x % 3;
    int rowid = blockIdx.x / 3;      // 1536 rows total
    int y = rowid % HH, b = rowid / HH;
    int px0 = chunk * 128 + pq * 4;
    // load input neighborhood: 2 ci x 3 ry x 6 cx
    float iv[2][3][6];
#pragma unroll
    for (int ci = 0; ci < 2; ci++) {
        const float* base = in + (b * 2 + ci) * HW;
#pragma unroll
        for (int ry = 0; ry < 3; ry++) {
            int yy = y + ry - 1; bool yok = (unsigned)yy < HH;
#pragma unroll
            for (int cx = 0; cx < 6; cx++) {
                int xx = px0 + cx - 1;
                iv[ci][ry][cx] = (yok && (unsigned)xx < WW) ? __ldg(base + yy * WW + xx) : 0.f;
            }
        }
    }
    float acc[4][8];
    float bz[8];
#pragma unroll
    for (int j = 0; j < 8; j++) bz[j] = __ldg(bias + cog * 8 + j);
#pragma unroll
    for (int px = 0; px < 4; px++)
#pragma unroll
        for (int j = 0; j < 8; j++) acc[px][j] = bz[j];
#pragma unroll
    for (int ci = 0; ci < 2; ci++)
#pragma unroll
        for (int ky = 0; ky < 3; ky++)
#pragma unroll
            for (int kx = 0; kx < 3; kx++) {
                int q = ci * 9 + ky * 3 + kx;
                const float4* wp = (const float4*)&ws[q * 64 + cog * 8];
                float4 wa = wp[0], wb = wp[1];
                float w8[8] = {wa.x, wa.y, wa.z, wa.w, wb.x, wb.y, wb.z, wb.w};
#pragma unroll
                for (int px = 0; px < 4; px++) {
                    float v = iv[ci][ky][kx + px];
#pragma unroll
                    for (int j = 0; j < 8; j++) acc[px][j] += v * w8[j];
                }
            }
#pragma unroll
    for (int px = 0; px < 4; px++) {
        size_t p = (size_t)b * HW + (size_t)y * WW + (px0 + px);
        __half2 h4[4];
#pragma unroll
        for (int j = 0; j < 8; j += 2)
            h4[j >> 1] = __floats2half2_rn(fmaxf(acc[px][j], 0.f), fmaxf(acc[px][j + 1], 0.f));
        *(uint4*)(g_h1n + p * 64 + cog * 8) = *(const uint4*)h4;
    }
}

// ---------------- conv2: 64 -> 64 via mma fp16, relu; M=32/warp (2 rows) ----------------
__global__ __launch_bounds__(128) void conv2_mma(const float* __restrict__ bias) {
    int x0 = blockIdx.x * 64, y0 = blockIdx.y * 2, b = blockIdx.z;
    int wid = threadIdx.x >> 5, lane = threadIdx.x & 31;
    int g = lane >> 2, t = lane & 3;
    int m = wid * 16 + g;
    float acc[2][8][4];
#pragma unroll
    for (int r = 0; r < 2; r++)
#pragma unroll
        for (int i = 0; i < 8; i++)
#pragma unroll
            for (int j = 0; j < 4; j++) acc[r][i][j] = 0.f;
#pragma unroll
    for (int ky = 0; ky < 3; ky++) {
        int ya = y0 + ky - 1, yb = ya + 1;
        bool oka = (unsigned)ya < HH, okb = (unsigned)yb < HH;
        const __half* rowa = g_h1n + (ptrdiff_t)(b * HH + ya) * (WW * 64);
        const __half* rowb = rowa + WW * 64;
#pragma unroll
        for (int kx = 0; kx < 3; kx++) {
            int x1 = x0 + kx - 1 + m, x2 = x1 + 8;
            bool ok1 = (unsigned)x1 < WW, ok2 = (unsigned)x2 < WW;
            const __half* wt = g_w2t + (ky * 3 + kx) * 4096;
            const __half* pa1 = rowa + (ptrdiff_t)x1 * 64;
            const __half* pa2 = rowa + (ptrdiff_t)x2 * 64;
            const __half* pb1 = rowb + (ptrdiff_t)x1 * 64;
            const __half* pb2 = rowb + (ptrdiff_t)x2 * 64;
#pragma unroll
            for (int kk = 0; kk < 4; kk++) {
                int ci = kk * 16 + 2 * t;
                unsigned A0 = (oka && ok1) ? *(const unsigned*)(pa1 + ci) : 0u;
                unsigned A1 = (oka && ok2) ? *(const unsigned*)(pa2 + ci) : 0u;
                unsigned A2 = (oka && ok1) ? *(const unsigned*)(pa1 + ci + 8) : 0u;
                unsigned A3 = (oka && ok2) ? *(const unsigned*)(pa2 + ci + 8) : 0u;
                unsigned C0 = (okb && ok1) ? *(const unsigned*)(pb1 + ci) : 0u;
                unsigned C1 = (okb && ok2) ? *(const unsigned*)(pb2 + ci) : 0u;
                unsigned C2 = (okb && ok1) ? *(const unsigned*)(pb1 + ci + 8) : 0u;
                unsigned C3 = (okb && ok2) ? *(const unsigned*)(pb2 + ci + 8) : 0u;
#pragma unroll
                for (int nt = 0; nt < 8; nt++) {
                    const __half* wn = wt + (nt * 8 + g) * 64 + ci;
                    unsigned w0 = *(const unsigned*)(wn);
                    unsigned w1 = *(const unsigned*)(wn + 8);
                    mma_f16(acc[0][nt], A0, A1, A2, A3, w0, w1);
                    mma_f16(acc[1][nt], C0, C1, C2, C3, w0, w1);
                }
            }
        }
    }
    int px1 = x0 + m;
#pragma unroll
    for (int r = 0; r < 2; r++) {
        int y = y0 + r;
        __half* o1 = g_h2n + ((size_t)(b * HH + y) * WW + px1) * 64;
        __half* o2 = o1 + 8 * 64;
#pragma unroll
        for (int nt = 0; nt < 8; nt++) {
            int n = nt * 8 + 2 * t;
            float b0 = __ldg(bias + n), b1 = __ldg(bias + n + 1);
            *(__half2*)(o1 + n) = __floats2half2_rn(fmaxf(acc[r][nt][0] + b0, 0.f), fmaxf(acc[r][nt][1] + b1, 0.f));
            *(__half2*)(o2 + n) = __floats2half2_rn(fmaxf(acc[r][nt][2] + b0, 0.f), fmaxf(acc[r][nt][3] + b1, 0.f));
        }
    }
}

// ---------------- conv3: 64 -> 2 via mma fp16; M=32/warp (2 rows) ----------------
__global__ __launch_bounds__(128) void conv3_mma(const float* __restrict__ bias) {
    int x0 = blockIdx.x * 64, y0 = blockIdx.y * 2, b = blockIdx.z;
    int wid = threadIdx.x >> 5, lane = threadIdx.x & 31;
    int g = lane >> 2, t = lane & 3;
    int m = wid * 16 + g;
    float acc[2][4];
#pragma unroll
    for (int r = 0; r < 2; r++)
#pragma unroll
        for (int j = 0; j < 4; j++) acc[r][j] = 0.f;
#pragma unroll
    for (int ky = 0; ky < 3; ky++) {
        int ya = y0 + ky - 1, yb = ya + 1;
        bool oka = (unsigned)ya < HH, okb = (unsigned)yb < HH;
        const __half* rowa = g_h2n + (ptrdiff_t)(b * HH + ya) * (WW * 64);
        const __half* rowb = rowa + WW * 64;
#pragma unroll
        for (int kx = 0; kx < 3; kx++) {
            int x1 = x0 + kx - 1 + m, x2 = x1 + 8;
            bool ok1 = (unsigned)x1 < WW, ok2 = (unsigned)x2 < WW;
            const __half* wt = g_w3t + (ky * 3 + kx) * 512;
            const __half* pa1 = rowa + (ptrdiff_t)x1 * 64;
            const __half* pa2 = rowa + (ptrdiff_t)x2 * 64;
            const __half* pb1 = rowb + (ptrdiff_t)x1 * 64;
            const __half* pb2 = rowb + (ptrdiff_t)x2 * 64;
#pragma unroll
            for (int kk = 0; kk < 4; kk++) {
                int ci = kk * 16 + 2 * t;
                unsigned A0 = (oka && ok1) ? *(const unsigned*)(pa1 + ci) : 0u;
                unsigned A1 = (oka && ok2) ? *(const unsigned*)(pa2 + ci) : 0u;
                unsigned A2 = (oka && ok1) ? *(const unsigned*)(pa1 + ci + 8) : 0u;
                unsigned A3 = (oka && ok2) ? *(const unsigned*)(pa2 + ci + 8) : 0u;
                unsigned C0 = (okb && ok1) ? *(const unsigned*)(pb1 + ci) : 0u;
                unsigned C1 = (okb && ok2) ? *(const unsigned*)(pb2 + ci) : 0u;
                unsigned C2 = (okb && ok1) ? *(const unsigned*)(pb1 + ci + 8) : 0u;
                unsigned C3 = (okb && ok2) ? *(const unsigned*)(pb2 + ci + 8) : 0u;
                const __half* wn = wt + g * 64 + ci;
                unsigned b0 = *(const unsigned*)(wn);
                unsigned b1 = *(const unsigned*)(wn + 8);
                mma_f16(acc[0], A0, A1, A2, A3, b0, b1);
                mma_f16(acc[1], C0, C1, C2, C3, b0, b1);
            }
        }
    }
    if (t == 0) {
        float b0 = __ldg(bias + 0), b1 = __ldg(bias + 1);
        int px1 = x0 + m, px2 = px1 + 8;
#pragma unroll
        for (int r = 0; r < 2; r++) {
            int base = (y0 + r) * WW;
            g_tmp2[(b * 2 + 0) * HW + base + px1] = acc[r][0] + b0;
            g_tmp2[(b * 2 + 1) * HW + base + px1] = acc[r][1] + b1;
            g_tmp2[(b * 2 + 0) * HW + base + px2] = acc[r][2] + b0;
            g_tmp2[(b * 2 + 1) * HW + base + px2] = acc[r][3] + b1;
        }
    }
}

// ---------------- GCN: s^T = (feat @ W1)^T, bf16, coalesced via smem transpose ----------------
__global__ __launch_bounds__(128) void gcn_s_k(const float* __restrict__ in,
                                               const float* __restrict__ W1) {
    __shared__ float w[36 * 64];
    __shared__ __nv_bfloat16 tb[16][136];
    for (int i = threadIdx.x; i < 2304; i += 128) w[i] = W1[i];
    __syncthreads();
    int idx = blockIdx.x * 128 + threadIdx.x;
    int n = idx & 4095, b = (idx >> 12) & 3, c = idx >> 14;
    int n0 = (blockIdx.x * 128) & 4095;
    int gy = n >> 6, gx = n & 63;
    const float* base = in + (b * 2 + c) * HW + (gy * 6) * WW + gx * 6;
    float f[36];
#pragma unroll
    for (int py = 0; py < 6; py++)
#pragma unroll
        for (int px = 0; px < 6; px++) f[py * 6 + px] = __ldg(base + py * WW + px);
    float acc[64];
#pragma unroll
    for (int o = 0; o < 64; o++) acc[o] = 0.f;
#pragma unroll
    for (int ff = 0; ff < 36; ff++) {
        float fv = f[ff];
        const float* wr = &w[ff * 64];
#pragma unroll
        for (int o = 0; o < 64; o++) acc[o] += fv * wr[o];
    }
    int nl = threadIdx.x;
    size_t orow = (size_t)(c * 256 + b * 64);
    for (int ch = 0; ch < 4; ch++) {
        __syncthreads();
#pragma unroll
        for (int o = 0; o < 16; o++) tb[o][nl] = __float2bfloat16(acc[ch * 16 + o]);
        __syncthreads();
        int r = nl >> 3, cw = (nl & 7) * 16;
        const uint4* src = (const uint4*)&tb[r][cw];
        uint4 v0 = src[0], v1 = src[1];
        uint4* dst = (uint4*)(g_st + (orow + ch * 16 + r) * NN + n0 + cw);
        dst[0] = v0; dst[1] = v1;
    }
}

// ---------------- GCN: s3^T = (g @ W3)^T, bf16, coalesced via smem transpose ----------------
__global__ __launch_bounds__(128) void gcn_s3_k(const float* __restrict__ W3) {
    __shared__ float w[64 * 36];
    __shared__ __nv_bfloat16 tb[36][136];
    for (int i = threadIdx.x; i < 2304; i += 128) w[i] = W3[i];
    __syncthreads();
    int idx = blockIdx.x * 128 + threadIdx.x;
    int n = idx & 4095, b = (idx >> 12) & 3, c = idx >> 14;
    int n0 = (blockIdx.x * 128) & 4095;
    const float* gb = g_g + (size_t)(c * NN + n) * 256 + b * 64;
    float acc[36];
#pragma unroll
    for (int o = 0; o < 36; o++) acc[o] = 0.f;
#pragma unroll
    for (int k = 0; k < 64; k += 4) {
        float4 g4 = *(const float4*)(gb + k);
        float gv[4] = {g4.x, g4.y, g4.z, g4.w};
#pragma unroll
        for (int kk = 0; kk < 4; kk++) {
            const float* wr = &w[(k + kk) * 36];
            float gvv = gv[kk];
#pragma unroll
            for (int o = 0; o < 36; o++) acc[o] += gvv * wr[o];
        }
    }
    int nl = threadIdx.x;
#pragma unroll
    for (int o = 0; o < 36; o++) tb[o][nl] = __float2bfloat16(acc[o]);
    __syncthreads();
    size_t orow = (size_t)(c * 144 + b * 36);
    for (int rr = nl; rr < 288; rr += 128) {
        int r = rr >> 3, cw = (rr & 7) * 16;
        const uint4* src = (const uint4*)&tb[r][cw];
        uint4 v0 = src[0], v1 = src[1];
        uint4* dst = (uint4*)(g_s3t + (orow + r) * NN + n0 + cw);
        dst[0] = v0; dst[1] = v1;
    }
}

// ---------------- adj GEMM via bf16 mma, M=32/warp, clamped N tail ----------------
template<int NT>
__global__ __launch_bounds__(128) void gemm_mma(int which, int Nvalid) {
    int c = blockIdx.z;
    const __nv_bfloat16* A = g_adjb + (size_t)c * NN * NN;
    const __nv_bfloat16* Bm; float* C; int Ncols;
    if (which == 0) { Bm = g_st  + (size_t)c * 256 * NN; C = g_g  + (size_t)c * NN * 256; Ncols = 256; }
    else            { Bm = g_s3t + (size_t)c * 144 * NN; C = g_t3 + (size_t)c * NN * 144; Ncols = 144; }
    int n0 = blockIdx.x * (NT * 8);
    int m0 = blockIdx.y * 128;
    int wid = threadIdx.x >> 5, lane = threadIdx.x & 31;
    int g = lane >> 2, t = lane & 3;
    int r1 = m0 + wid * 32 + g;
    const __nv_bfloat16* ar0 = A + (size_t)r1 * NN;
    const __nv_bfloat16* ar1 = ar0 + (size_t)8 * NN;
    const __nv_bfloat16* ar2 = ar0 + (size_t)16 * NN;
    const __nv_bfloat16* ar3 = ar0 + (size_t)24 * NN;
    const __nv_bfloat16* br[NT];
#pragma unroll
    for (int nt = 0; nt < NT; nt++) {
        int nc = n0 + nt * 8 + g;
        br[nt] = Bm + (size_t)(nc < Nvalid ? nc : Nvalid - 1) * NN;
    }
    float acc[2][NT][4];
#pragma unroll
    for (int r = 0; r < 2; r++)
#pragma unroll
        for (int i = 0; i < NT; i++)
#pragma unroll
            for (int j = 0; j < 4; j++) acc[r][i][j] = 0.f;
#pragma unroll 2
    for (int k0 = 0; k0 < NN; k0 += 16) {
        int kb = k0 + 2 * t;
        unsigned a0 = *(const unsigned*)(ar0 + kb);
        unsigned a1 = *(const unsigned*)(ar1 + kb);
        unsigned a2 = *(const unsigned*)(ar0 + kb + 8);
        unsigned a3 = *(const unsigned*)(ar1 + kb + 8);
        unsigned c0 = *(const unsigned*)(ar2 + kb);
        unsigned c1 = *(const unsigned*)(ar3 + kb);
        unsigned c2 = *(const unsigned*)(ar2 + kb + 8);
        unsigned c3 = *(const unsigned*)(ar3 + kb + 8);
#pragma unroll
        for (int nt = 0; nt < NT; nt++) {
            unsigned b0 = *(const unsigned*)(br[nt] + kb);
            unsigned b1 = *(const unsigned*)(br[nt] + kb + 8);
            mma_bf16(acc[0][nt], a0, a1, a2, a3, b0, b1);
            mma_bf16(acc[1][nt], c0, c1, c2, c3, b0, b1);
        }
    }
#pragma unroll
    for (int r = 0; r < 2; r++) {
        int ra = r1 + r * 16, rb = ra + 8;
#pragma unroll
        for (int nt = 0; nt < NT; nt++) {
            if (n0 + nt * 8 >= Nvalid) continue;
            int n = n0 + nt * 8 + 2 * t;
            float v0 = acc[r][nt][0], v1 = acc[r][nt][1], v2 = acc[r][nt][2], v3 = acc[r][nt][3];
            if (which == 0) { v0 = fmaxf(v0, 0.f); v1 = fmaxf(v1, 0.f); v2 = fmaxf(v2, 0.f); v3 = fmaxf(v3, 0.f); }
            *(float2*)(C + (size_t)ra * Ncols + n) = make_float2(v0, v1);
            *(float2*)(C + (size_t)rb * Ncols + n) = make_float2(v2, v3);
        }
    }
}

// ---------------- combine: out = in + (1-arf)*tmp2 + arf*tmp3 ----------------
__global__ __launch_bounds__(256) void combine_k(const float* __restrict__ in,
                                                 const float* __restrict__ arf) {
    int g = blockIdx.x * 256 + threadIdx.x;
    int p = g % HW, b = g / HW;
    int x = p % WW, y = p / WW;
    float a = __ldg(arf);
    int gy = y / 6, py = y - gy * 6, gx = x / 6, px = x - gx * 6;
    int n = gy * 64 + gx, f = py * 6 + px;
#pragma unroll
    for (int c = 0; c < 2; c++) {
        float t3v = g_t3[(size_t)(c * NN + n) * 144 + b * 36 + f];
        int li = (b * 2 + c) * HW + p;
        g_oimg[li] = in[li] + (1.f - a) * g_tmp2[li] + a * t3v;
    }
}

__device__ __forceinline__ float2 cadd(float2 a, float2 b) { return make_float2(a.x + b.x, a.y + b.y); }
__device__ __forceinline__ float2 csub(float2 a, float2 b) { return make_float2(a.x - b.x, a.y - b.y); }

// ---------------- fwd row FFT; fused z=(-1)^(x+y)*oimg*csm at load ----------------
__global__ __launch_bounds__(192) void fft_row_fwd_k(const float* __restrict__ csr,
                                                     const float* __restrict__ csi) {
    __shared__ float2 sb[384];
    int line = blockIdx.x;                 // img*384 + y
    float2* base = g_k + (size_t)line * 384;
    int tid = threadIdx.x;
    {
        int img = line / HH, y = line % HH;
        int b = img & 3, c = img >> 2;
        const float* o0 = g_oimg + (size_t)(b * 2 + 0) * HW + y * WW;
        const float* o1 = g_oimg + (size_t)(b * 2 + 1) * HW + y * WW;
        const float* cr = csr + (size_t)(b * CCH + c) * HW + y * WW;
        const float* ci = csi + (size_t)(b * CCH + c) * HW + y * WW;
        for (int i = tid; i < 384; i += 192) {
            float orr = o0[i], oii = o1[i];
            float crv = __ldg(cr + i), civ = __ldg(ci + i);
            float sgn = ((i + y) & 1) ? -1.f : 1.f;
            float2 z = make_float2(sgn * (orr * crv - oii * civ), sgn * (orr * civ + oii * crv));
            int r = i % 3, q = i / 3;
            sb[r * 128 + q] = z;
        }
    }
    __syncthreads();
    int r = tid >> 6, bf = tid & 63, off = r << 7;
#pragma unroll
    for (int len = 128; len >= 2; len >>= 1) {
        int h = len >> 1;
        int grp = bf / h, t = bf - grp * h;
        int i1 = off + grp * len + t;
        float2 u = sb[i1], v = sb[i1 + h];
        sb[i1] = cadd(u, v);
        float2 d = csub(u, v);
        float2 w = g_tw128[t * (128 / len)];
        sb[i1 + h] = make_float2(d.x * w.x - d.y * w.y, d.x * w.y + d.y * w.x);
        __syncthreads();
    }
    for (int k = tid; k < 384; k += 192) {
        int k0 = k & 127;
        int rv = __brev((unsigned)k0) >> 25;
        float2 y0 = sb[rv], y1 = sb[128 + rv], y2 = sb[256 + rv];
        float2 c1 = g_tw384[k], c2 = g_tw384[(2 * k) % 384];
        float xr = y0.x + c1.x * y1.x - c1.y * y1.y + c2.x * y2.x - c2.y * y2.y;
        float xi = y0.y + c1.x * y1.y + c1.y * y1.x + c2.x * y2.y + c2.y * y2.x;
        base[k] = make_float2(xr, xi);
    }
}

// ---------------- column FFT; DC=1: apply data consistency at load ----------------
template<int INV, int DC>
__global__ __launch_bounds__(192) void fft_col_k(const int* __restrict__ mask,
                                                 const float* __restrict__ tkr,
                                                 const float* __restrict__ tki) {
    __shared__ float2 sb[8 * 384];
    int img = blockIdx.x / 48, cg = blockIdx.x % 48;
    float2* base = g_k + (size_t)img * HW + cg * 8;
    int tid = threadIdx.x;
    for (int i = tid; i < 3072; i += 192) {
        int col = i & 7, yy = i >> 3;
        float2 Z = base[(size_t)yy * 384 + col];
        if (DC) {
            int gx = cg * 8 + col;
            int p = yy * 384 + gx;
            float mv = (float)__ldg(mask + p);
            float sgn = ((gx + yy) & 1) ? -1.f : 1.f;
            float coef = 384.f * 0.999999f * mv * sgn;
            float om = 1.f - mv;
            size_t gidx = (size_t)img * HW + p;
            Z.x = om * Z.x + coef * __ldg(tkr + gidx);
            Z.y = om * Z.y + coef * __ldg(tki + gidx);
        }
        int r = yy % 3, q = yy / 3;
        sb[col * 384 + r * 128 + q] = Z;
    }
    __syncthreads();
#pragma unroll
    for (int len = 128; len >= 2; len >>= 1) {
        int h = len >> 1;
        for (int widx = tid; widx < 1536; widx += 192) {
            int seg = widx >> 6, bf = widx & 63;
            int boff = (seg / 3) * 384 + (seg % 3) * 128;
            int grp = bf / h, t = bf - grp * h;
            int i1 = boff + grp * len + t;
            float2 u = sb[i1], v = sb[i1 + h];
            sb[i1] = cadd(u, v);
            float2 d = csub(u, v);
            float2 w = g_tw128[t * (128 / len)];
            float wy = INV ? -w.y : w.y;
            sb[i1 + h] = make_float2(d.x * w.x - d.y * wy, d.x * wy + d.y * w.x);
        }
        __syncthreads();
    }
    for (int i = tid; i < 3072; i += 192) {
        int col = i & 7, k = i >> 3;
        int k0 = k & 127;
        int rv = __brev((unsigned)k0) >> 25;
        int cb = col * 384;
        float2 y0 = sb[cb + rv], y1 = sb[cb + 128 + rv], y2 = sb[cb + 256 + rv];
        float2 c1 = g_tw384[k], c2 = g_tw384[(2 * k) % 384];
        float s1 = INV ? -c1.y : c1.y, s2 = INV ? -c2.y : c2.y;
        float xr = y0.x + c1.x * y1.x - s1 * y1.y + c2.x * y2.x - s2 * y2.y;
        float xi = y0.y + c1.x * y1.y + s1 * y1.x + c2.x * y2.y + s2 * y2.x;
        if (INV) { xr *= (1.f / 384.f); xi *= (1.f / 384.f); }
        base[(size_t)k * 384 + col] = make_float2(xr, xi);
    }
}

// ---------------- fused inverse row FFT (12 coils) + coil combine ----------------
// grid = 4*384 (b,y), 384 threads
__global__ __launch_bounds__(384) void invrow_final_k(const float* __restrict__ csr,
                                                      const float* __restrict__ csi,
                                                      float* __restrict__ out) {
    __shared__ float2 sb[12][384];
    int y = blockIdx.x % HH, b = blockIdx.x / HH;
    int tid = threadIdx.x;
    int r0 = tid % 3, q0 = tid / 3;
#pragma unroll
    for (int c = 0; c < CCH; c++) {
        float2 z = g_k[((size_t)(c * BSZ + b)) * HW + (size_t)y * 384 + tid];
        sb[c][r0 * 128 + q0] = z;
    }
    __syncthreads();
#pragma unroll
    for (int len = 128; len >= 2; len >>= 1) {
        int h = len >> 1;
        for (int widx = tid; widx < 2304; widx += 384) {
            int line = widx / 192, bf = widx % 192;
            int seg = bf >> 6, b6 = bf & 63;
            int grp = b6 / h, t = b6 - grp * h;
            int i1 = seg * 128 + grp * len + t;
            float2 u = sb[line][i1], v = sb[line][i1 + h];
            sb[line][i1] = cadd(u, v);
            float2 d = csub(u, v);
            float2 w = g_tw128[t * (128 / len)];
            sb[line][i1 + h] = make_float2(d.x * w.x + d.y * w.y, -d.x * w.y + d.y * w.x);
        }
        __syncthreads();
    }
    int k = tid;
    int k0 = k & 127;
    int rv = __brev((unsigned)k0) >> 25;
    float2 c1 = g_tw384[k], c2 = g_tw384[(2 * k) % 384];
    float s1 = -c1.y, s2 = -c2.y;
    float rr = 0.f, ri = 0.f;
    const float* crb = csr + (size_t)b * CCH * HW + (size_t)y * WW + k;
    const float* cib = csi + (size_t)b * CCH * HW + (size_t)y * WW + k;
#pragma unroll
    for (int c = 0; c < CCH; c++) {
        float2 y0 = sb[c][rv], y1 = sb[c][128 + rv], y2 = sb[c][256 + rv];
        float xr = (y0.x + c1.x * y1.x - s1 * y1.y + c2.x * y2.x - s2 * y2.y) * (1.f / 384.f);
        float xi = (y0.y + c1.x * y1.y + s1 * y1.x + c2.x * y2.y + s2 * y2.x) * (1.f / 384.f);
        float cr = __ldg(crb + (size_t)c * HW);
        float ci = __ldg(cib + (size_t)c * HW);
        rr += xr * cr + xi * ci;
        ri += xi * cr - xr * ci;
    }
    float sgn = ((k + y) & 1) ? -1.f : 1.f;
    out[(size_t)(b * 2 + 0) * HW + (size_t)y * WW + k] = sgn * rr;
    out[(size_t)(b * 2 + 1) * HW + (size_t)y * WW + k] = sgn * ri;
}

// ---------------- launch ----------------
extern "C" void kernel_launch(void* const* d_in, const int* in_sizes, int n_in,
                              void* d_out, int out_size) {
    (void)in_sizes; (void)n_in; (void)out_size;
    const float* input = (const float*)d_in[0];
    const float* adj   = (const float*)d_in[1];
    const int*   mask  = (const int*)  d_in[2];
    const float* csr   = (const float*)d_in[3];
    const float* csi   = (const float*)d_in[4];
    const float* tkr   = (const float*)d_in[5];
    const float* tki   = (const float*)d_in[6];
    const float* W1    = (const float*)d_in[7];
    const float* W3    = (const float*)d_in[8];
    const float* arf   = (const float*)d_in[9];
    const float* cw1   = (const float*)d_in[10];
    const float* cb1   = (const float*)d_in[11];
    const float* cw2   = (const float*)d_in[12];
    const float* cb2   = (const float*)d_in[13];
    const float* cw3   = (const float*)d_in[14];
    const float* cb3   = (const float*)d_in[15];
    float* out = (float*)d_out;

    init_tw_k<<<1, 384>>>();
    prep_w_k<<<144, 256>>>(cw2, cw3);
    adj_cvt_k<<<32768, 256>>>(adj);

    // CNN branch
    conv1_k<<<4608, 256>>>(input, cw1, cb1);
    conv2_mma<<<dim3(6, 192, 4), 128>>>(cb2);
    conv3_mma<<<dim3(6, 192, 4), 128>>>(cb3);

    // GCN branch
    gcn_s_k<<<256, 128>>>(input, W1);
    gemm_mma<8><<<dim3(4, 32, 2), 128>>>(0, 256);   // g = relu(adj @ s)
    gcn_s3_k<<<256, 128>>>(W3);
    gemm_mma<8><<<dim3(3, 32, 2), 128>>>(1, 144);   // t3, clamped tail

    // combine + FFT chain
    combine_k<<<2304, 256>>>(input, arf);
    fft_row_fwd_k<<<48 * 384, 192>>>(csr, csi);
    fft_col_k<0, 0><<<48 * 48, 192>>>(nullptr, nullptr, nullptr);
    fft_col_k<1, 1><<<48 * 48, 192>>>(mask, tkr, tki);
    invrow_final_k<<<4 * 384, 384>>>(csr, csi, out);
}

// round 8
// speedup vs baseline: 2.9488x; 1.3283x over previous
#include <cuda_runtime.h>
#include <cuda_fp16.h>
#include <cuda_bf16.h>
#include <math.h>
#include <stdint.h>
#include <stddef.h>

#define BSZ 4
#define CCH 12
#define HH 384
#define WW 384
#define HW (HH*WW)
#define NN 4096

// ---------------- static device scratch (no allocs allowed) ----------------
__device__ __half         g_h1n[(size_t)BSZ*HW*64];   // conv1 out, NHWC fp16
__device__ __half         g_h2n[(size_t)BSZ*HW*64];   // conv2 out, NHWC fp16
__device__ __nv_bfloat16  g_adjb[(size_t)2*NN*NN];    // adj bf16
__device__ __half         g_w2t[9*64*64];             // conv2 w [tap][co][ci]
__device__ __half         g_w3t[9*8*64];              // conv3 w [tap][o pad8][ci]
__device__ __nv_bfloat16  g_st [(size_t)2*256*NN];    // s^T  [c][b*64+o][m]
__device__ __nv_bfloat16  g_s3t[(size_t)2*144*NN];    // s3^T [c][b*36+o][m]
__device__ float          g_g  [(size_t)2*NN*256];    // relu(adj@s) [c][m][256]
__device__ float          g_t3 [(size_t)2*NN*144];    // adj@s3 [c][m][144]
__device__ float          g_tmp2[BSZ*2*HW];
__device__ float          g_oimg[BSZ*2*HW];
__device__ float2         g_k[(size_t)CCH*BSZ*HW];
__device__ float2         g_tw128[64];
__device__ float2         g_tw384[384];

// ---------------- mma / ldmatrix wrappers ----------------
__device__ __forceinline__ void mma_f16(float c[4], unsigned a0, unsigned a1,
                                        unsigned a2, unsigned a3,
                                        unsigned b0, unsigned b1) {
    asm volatile("mma.sync.aligned.m16n8k16.row.col.f32.f16.f16.f32 "
        "{%0,%1,%2,%3}, {%4,%5,%6,%7}, {%8,%9}, {%0,%1,%2,%3};"
        : "+f"(c[0]), "+f"(c[1]), "+f"(c[2]), "+f"(c[3])
        : "r"(a0), "r"(a1), "r"(a2), "r"(a3), "r"(b0), "r"(b1));
}
__device__ __forceinline__ void mma_bf16(float c[4], unsigned a0, unsigned a1,
                                         unsigned a2, unsigned a3,
                                         unsigned b0, unsigned b1) {
    asm volatile("mma.sync.aligned.m16n8k16.row.col.f32.bf16.bf16.f32 "
        "{%0,%1,%2,%3}, {%4,%5,%6,%7}, {%8,%9}, {%0,%1,%2,%3};"
        : "+f"(c[0]), "+f"(c[1]), "+f"(c[2]), "+f"(c[3])
        : "r"(a0), "r"(a1), "r"(a2), "r"(a3), "r"(b0), "r"(b1));
}
__device__ __forceinline__ void ldsm_x4(unsigned r[4], uint32_t a) {
    asm volatile("ldmatrix.sync.aligned.m8n8.x4.shared.b16 {%0,%1,%2,%3}, [%4];"
        : "=r"(r[0]), "=r"(r[1]), "=r"(r[2]), "=r"(r[3]) : "r"(a));
}
__device__ __forceinline__ void ldsm_x2(unsigned& r0, unsigned& r1, uint32_t a) {
    asm volatile("ldmatrix.sync.aligned.m8n8.x2.shared.b16 {%0,%1}, [%2];"
        : "=r"(r0), "=r"(r1) : "r"(a));
}

// ---------------- init ----------------
__global__ void init_tw_k() {
    int t = threadIdx.x;
    if (t < 64) { float s, c; sincospif(-(float)t / 64.f, &s, &c);  g_tw128[t] = make_float2(c, s); }
    {            float s, c; sincospif(-(float)t / 192.f, &s, &c); g_tw384[t] = make_float2(c, s); }
}
__global__ void prep_w_k(const float* __restrict__ cw2, const float* __restrict__ cw3) {
    int i = blockIdx.x * 256 + threadIdx.x;
    if (i < 9 * 64 * 64) {
        int tap = i / 4096, r = i % 4096, co = r >> 6, ci = r & 63;
        g_w2t[i] = __float2half(cw2[(co * 64 + ci) * 9 + tap]);
    }
    if (i < 9 * 8 * 64) {
        int tap = i / 512, r = i % 512, o = r >> 6, ci = r & 63;
        g_w3t[i] = __float2half((o < 2) ? cw3[(o * 64 + ci) * 9 + tap] : 0.f);
    }
}
__global__ __launch_bounds__(256) void adj_cvt_k(const float* __restrict__ adj) {
    size_t i = ((size_t)blockIdx.x * 256 + threadIdx.x) * 4;
    float4 v = *(const float4*)(adj + i);
    __nv_bfloat162* o = (__nv_bfloat162*)(g_adjb + i);
    o[0] = __floats2bfloat162_rn(v.x, v.y);
    o[1] = __floats2bfloat162_rn(v.z, v.w);
}

// ---------------- conv1: 2 -> 64, relu; 4 px x 8 ch per thread ----------------
__global__ __launch_bounds__(256) void conv1_k(const float* __restrict__ in,
                                               const float* __restrict__ w,
                                               const float* __restrict__ bias) {
    __shared__ float ws[18 * 64];   // [q=ci*9+tap][co]
    for (int i = threadIdx.x; i < 1152; i += 256) {
        int co = i / 18, q = i % 18;
        ws[q * 64 + co] = w[i];
    }
    __syncthreads();
    int tid = threadIdx.x;
    int cog = tid & 7;
    int pq  = tid >> 3;
    int chunk = blockIdx.x % 3;
    int rowid = blockIdx.x / 3;
    int y = rowid % HH, b = rowid / HH;
    int px0 = chunk * 128 + pq * 4;
    float iv[2][3][6];
#pragma unroll
    for (int ci = 0; ci < 2; ci++) {
        const float* base = in + (b * 2 + ci) * HW;
#pragma unroll
        for (int ry = 0; ry < 3; ry++) {
            int yy = y + ry - 1; bool yok = (unsigned)yy < HH;
#pragma unroll
            for (int cx = 0; cx < 6; cx++) {
                int xx = px0 + cx - 1;
                iv[ci][ry][cx] = (yok && (unsigned)xx < WW) ? __ldg(base + yy * WW + xx) : 0.f;
            }
        }
    }
    float acc[4][8];
    float bz[8];
#pragma unroll
    for (int j = 0; j < 8; j++) bz[j] = __ldg(bias + cog * 8 + j);
#pragma unroll
    for (int px = 0; px < 4; px++)
#pragma unroll
        for (int j = 0; j < 8; j++) acc[px][j] = bz[j];
#pragma unroll
    for (int ci = 0; ci < 2; ci++)
#pragma unroll
        for (int ky = 0; ky < 3; ky++)
#pragma unroll
            for (int kx = 0; kx < 3; kx++) {
                int q = ci * 9 + ky * 3 + kx;
                const float4* wp = (const float4*)&ws[q * 64 + cog * 8];
                float4 wa = wp[0], wb = wp[1];
                float w8[8] = {wa.x, wa.y, wa.z, wa.w, wb.x, wb.y, wb.z, wb.w};
#pragma unroll
                for (int px = 0; px < 4; px++) {
                    float v = iv[ci][ky][kx + px];
#pragma unroll
                    for (int j = 0; j < 8; j++) acc[px][j] += v * w8[j];
                }
            }
#pragma unroll
    for (int px = 0; px < 4; px++) {
        size_t p = (size_t)b * HW + (size_t)y * WW + (px0 + px);
        __half2 h4[4];
#pragma unroll
        for (int j = 0; j < 8; j += 2)
            h4[j >> 1] = __floats2half2_rn(fmaxf(acc[px][j], 0.f), fmaxf(acc[px][j + 1], 0.f));
        *(uint4*)(g_h1n + p * 64 + cog * 8) = *(const uint4*)h4;
    }
}

// ---------------- conv2: 64->64 mma fp16, smem+ldmatrix, M=32/warp (2 rows) ----------------
// grid (6, 192, 4), 128 thr = 4 warps; x strip 64, y pair
__global__ __launch_bounds__(128) void conv2_mma(const float* __restrict__ bias) {
    __shared__ uint4 s_a[4 * 66 * 8];   // [row 4][px 66][chunk 8 swizzled], 33.8KB
    __shared__ uint4 s_b[512];          // [co 64][chunk 8 swizzled], 8KB
    int x0 = blockIdx.x * 64, y0 = blockIdx.y * 2, b = blockIdx.z;
    int tid = threadIdx.x, wid = tid >> 5, lane = tid & 31;
    int g = lane >> 2, t = lane & 3;
    // stage A tile (input rows y0-1..y0+2, px x0-1..x0+64), halo zero
    for (int idx = tid; idx < 2112; idx += 128) {
        int r = idx / 528, rem = idx % 528, p = rem >> 3, cc = rem & 7;
        int gx = x0 - 1 + p, yy = y0 - 1 + r;
        uint4 v = make_uint4(0, 0, 0, 0);
        if ((unsigned)gx < WW && (unsigned)yy < HH)
            v = *(const uint4*)(g_h1n + ((size_t)(b * HH + yy) * WW + gx) * 64 + cc * 8);
        s_a[(r * 66 + p) * 8 + (cc ^ (p & 7))] = v;
    }
    uint32_t sa = (uint32_t)__cvta_generic_to_shared(s_a);
    uint32_t sb = (uint32_t)__cvta_generic_to_shared(s_b);
    int lrow = lane & 7, msel = lane >> 3;
    int a_pofs = ((msel & 1) << 3) + lrow;   // pixel offset in fragment
    int a_hi = msel >> 1;                    // k high-chunk bit
    int b_hi = (lane >> 3) & 1;
    float acc[2][8][4];
#pragma unroll
    for (int r = 0; r < 2; r++)
#pragma unroll
        for (int i = 0; i < 8; i++)
#pragma unroll
            for (int j = 0; j < 4; j++) acc[r][i][j] = 0.f;

    for (int ky = 0; ky < 3; ky++)
        for (int kx = 0; kx < 3; kx++) {
            int tap = ky * 3 + kx;
            __syncthreads();
            for (int idx = tid; idx < 512; idx += 128) {
                int co = idx >> 3, cc = idx & 7;
                s_b[co * 8 + (cc ^ (co & 7))] =
                    *(const uint4*)(g_w2t + tap * 4096 + co * 64 + cc * 8);
            }
            __syncthreads();
            int p = wid * 16 + kx + a_pofs;
            int psw = p & 7;
            int arow0 = (ky * 66 + p) * 8, arow1 = arow0 + 66 * 8;
#pragma unroll
            for (int kk = 0; kk < 4; kk++) {
                unsigned a0[4], a1[4];
                int chunk = 2 * kk + a_hi;
                ldsm_x4(a0, sa + (arow0 + (chunk ^ psw)) * 16);
                ldsm_x4(a1, sa + (arow1 + (chunk ^ psw)) * 16);
                int bch = 2 * kk + b_hi;
#pragma unroll
                for (int nt = 0; nt < 8; nt++) {
                    unsigned b0, b1;
                    ldsm_x2(b0, b1, sb + (nt * 64 + lrow * 8 + (bch ^ lrow)) * 16);
                    mma_f16(acc[0][nt], a0[0], a0[1], a0[2], a0[3], b0, b1);
                    mma_f16(acc[1][nt], a1[0], a1[1], a1[2], a1[3], b0, b1);
                }
            }
        }
    int px1 = x0 + wid * 16 + g;
#pragma unroll
    for (int r = 0; r < 2; r++) {
        int y = y0 + r;
        __half* o1 = g_h2n + ((size_t)(b * HH + y) * WW + px1) * 64;
        __half* o2 = o1 + 8 * 64;
#pragma unroll
        for (int nt = 0; nt < 8; nt++) {
            int n = nt * 8 + 2 * t;
            float b0 = __ldg(bias + n), b1 = __ldg(bias + n + 1);
            *(__half2*)(o1 + n) = __floats2half2_rn(fmaxf(acc[r][nt][0] + b0, 0.f), fmaxf(acc[r][nt][1] + b1, 0.f));
            *(__half2*)(o2 + n) = __floats2half2_rn(fmaxf(acc[r][nt][2] + b0, 0.f), fmaxf(acc[r][nt][3] + b1, 0.f));
        }
    }
}

// ---------------- conv3: 64->2 mma fp16, smem+ldmatrix, M=32/warp ----------------
__global__ __launch_bounds__(128) void conv3_mma(const float* __restrict__ bias) {
    __shared__ uint4 s_a[4 * 66 * 8];   // 33.8KB
    __shared__ uint4 s_b3[576];         // [tap 9][o 8][chunk 8 swizzled], 9.2KB
    int x0 = blockIdx.x * 64, y0 = blockIdx.y * 2, b = blockIdx.z;
    int tid = threadIdx.x, wid = tid >> 5, lane = tid & 31;
    int g = lane >> 2, t = lane & 3;
    for (int idx = tid; idx < 2112; idx += 128) {
        int r = idx / 528, rem = idx % 528, p = rem >> 3, cc = rem & 7;
        int gx = x0 - 1 + p, yy = y0 - 1 + r;
        uint4 v = make_uint4(0, 0, 0, 0);
        if ((unsigned)gx < WW && (unsigned)yy < HH)
            v = *(const uint4*)(g_h2n + ((size_t)(b * HH + yy) * WW + gx) * 64 + cc * 8);
        s_a[(r * 66 + p) * 8 + (cc ^ (p & 7))] = v;
    }
    for (int idx = tid; idx < 576; idx += 128) {
        int tap = idx / 64, rem = idx % 64, co = rem >> 3, cc = rem & 7;
        s_b3[tap * 64 + co * 8 + (cc ^ co)] =
            *(const uint4*)(g_w3t + tap * 512 + co * 64 + cc * 8);
    }
    __syncthreads();
    uint32_t sa = (uint32_t)__cvta_generic_to_shared(s_a);
    uint32_t sb = (uint32_t)__cvta_generic_to_shared(s_b3);
    int lrow = lane & 7, msel = lane >> 3;
    int a_pofs = ((msel & 1) << 3) + lrow;
    int a_hi = msel >> 1;
    int b_hi = (lane >> 3) & 1;
    float acc[2][4];
#pragma unroll
    for (int r = 0; r < 2; r++)
#pragma unroll
        for (int j = 0; j < 4; j++) acc[r][j] = 0.f;
    for (int ky = 0; ky < 3; ky++)
        for (int kx = 0; kx < 3; kx++) {
            int tap = ky * 3 + kx;
            int p = wid * 16 + kx + a_pofs;
            int psw = p & 7;
            int arow0 = (ky * 66 + p) * 8, arow1 = arow0 + 66 * 8;
#pragma unroll
            for (int kk = 0; kk < 4; kk++) {
                unsigned a0[4], a1[4];
                int chunk = 2 * kk + a_hi;
                ldsm_x4(a0, sa + (arow0 + (chunk ^ psw)) * 16);
                ldsm_x4(a1, sa + (arow1 + (chunk ^ psw)) * 16);
                unsigned b0, b1;
                int bch = 2 * kk + b_hi;
                ldsm_x2(b0, b1, sb + (tap * 64 + lrow * 8 + (bch ^ lrow)) * 16);
                mma_f16(acc[0], a0[0], a0[1], a0[2], a0[3], b0, b1);
                mma_f16(acc[1], a1[0], a1[1], a1[2], a1[3], b0, b1);
            }
        }
    if (t == 0) {
        float b0 = __ldg(bias + 0), b1 = __ldg(bias + 1);
        int px1 = x0 + wid * 16 + g, px2 = px1 + 8;
#pragma unroll
        for (int r = 0; r < 2; r++) {
            int base = (y0 + r) * WW;
            g_tmp2[(b * 2 + 0) * HW + base + px1] = acc[r][0] + b0;
            g_tmp2[(b * 2 + 1) * HW + base + px1] = acc[r][1] + b1;
            g_tmp2[(b * 2 + 0) * HW + base + px2] = acc[r][2] + b0;
            g_tmp2[(b * 2 + 1) * HW + base + px2] = acc[r][3] + b1;
        }
    }
}

// ---------------- GCN: s^T = (feat @ W1)^T, bf16, coalesced via smem transpose ----------------
__global__ __launch_bounds__(128) void gcn_s_k(const float* __restrict__ in,
                                               const float* __restrict__ W1) {
    __shared__ float w[36 * 64];
    __shared__ __nv_bfloat16 tb[16][136];
    for (int i = threadIdx.x; i < 2304; i += 128) w[i] = W1[i];
    __syncthreads();
    int idx = blockIdx.x * 128 + threadIdx.x;
    int n = idx & 4095, b = (idx >> 12) & 3, c = idx >> 14;
    int n0 = (blockIdx.x * 128) & 4095;
    int gy = n >> 6, gx = n & 63;
    const float* base = in + (b * 2 + c) * HW + (gy * 6) * WW + gx * 6;
    float f[36];
#pragma unroll
    for (int py = 0; py < 6; py++)
#pragma unroll
        for (int px = 0; px < 6; px++) f[py * 6 + px] = __ldg(base + py * WW + px);
    float acc[64];
#pragma unroll
    for (int o = 0; o < 64; o++) acc[o] = 0.f;
#pragma unroll
    for (int ff = 0; ff < 36; ff++) {
        float fv = f[ff];
        const float* wr = &w[ff * 64];
#pragma unroll
        for (int o = 0; o < 64; o++) acc[o] += fv * wr[o];
    }
    int nl = threadIdx.x;
    size_t orow = (size_t)(c * 256 + b * 64);
    for (int ch = 0; ch < 4; ch++) {
        __syncthreads();
#pragma unroll
        for (int o = 0; o < 16; o++) tb[o][nl] = __float2bfloat16(acc[ch * 16 + o]);
        __syncthreads();
        int r = nl >> 3, cw = (nl & 7) * 16;
        const uint4* src = (const uint4*)&tb[r][cw];
        uint4 v0 = src[0], v1 = src[1];
        uint4* dst = (uint4*)(g_st + (orow + ch * 16 + r) * NN + n0 + cw);
        dst[0] = v0; dst[1] = v1;
    }
}

// ---------------- GCN: s3^T = (g @ W3)^T, bf16, coalesced via smem transpose ----------------
__global__ __launch_bounds__(128) void gcn_s3_k(const float* __restrict__ W3) {
    __shared__ float w[64 * 36];
    __shared__ __nv_bfloat16 tb[36][136];
    for (int i = threadIdx.x; i < 2304; i += 128) w[i] = W3[i];
    __syncthreads();
    int idx = blockIdx.x * 128 + threadIdx.x;
    int n = idx & 4095, b = (idx >> 12) & 3, c = idx >> 14;
    int n0 = (blockIdx.x * 128) & 4095;
    const float* gb = g_g + (size_t)(c * NN + n) * 256 + b * 64;
    float acc[36];
#pragma unroll
    for (int o = 0; o < 36; o++) acc[o] = 0.f;
#pragma unroll
    for (int k = 0; k < 64; k += 4) {
        float4 g4 = *(const float4*)(gb + k);
        float gv[4] = {g4.x, g4.y, g4.z, g4.w};
#pragma unroll
        for (int kk = 0; kk < 4; kk++) {
            const float* wr = &w[(k + kk) * 36];
            float gvv = gv[kk];
#pragma unroll
            for (int o = 0; o < 36; o++) acc[o] += gvv * wr[o];
        }
    }
    int nl = threadIdx.x;
#pragma unroll
    for (int o = 0; o < 36; o++) tb[o][nl] = __float2bfloat16(acc[o]);
    __syncthreads();
    size_t orow = (size_t)(c * 144 + b * 36);
    for (int rr = nl; rr < 288; rr += 128) {
        int r = rr >> 3, cw = (rr & 7) * 16;
        const uint4* src = (const uint4*)&tb[r][cw];
        uint4 v0 = src[0], v1 = src[1];
        uint4* dst = (uint4*)(g_s3t + (orow + r) * NN + n0 + cw);
        dst[0] = v0; dst[1] = v1;
    }
}

// ---------------- adj GEMM via bf16 mma, M=32/warp, clamped N tail ----------------
template<int NT>
__global__ __launch_bounds__(128) void gemm_mma(int which, int Nvalid) {
    int c = blockIdx.z;
    const __nv_bfloat16* A = g_adjb + (size_t)c * NN * NN;
    const __nv_bfloat16* Bm; float* C; int Ncols;
    if (which == 0) { Bm = g_st  + (size_t)c * 256 * NN; C = g_g  + (size_t)c * NN * 256; Ncols = 256; }
    else            { Bm = g_s3t + (size_t)c * 144 * NN; C = g_t3 + (size_t)c * NN * 144; Ncols = 144; }
    int n0 = blockIdx.x * (NT * 8);
    int m0 = blockIdx.y * 128;
    int wid = threadIdx.x >> 5, lane = threadIdx.x & 31;
    int g = lane >> 2, t = lane & 3;
    int r1 = m0 + wid * 32 + g;
    const __nv_bfloat16* ar0 = A + (size_t)r1 * NN;
    const __nv_bfloat16* ar1 = ar0 + (size_t)8 * NN;
    const __nv_bfloat16* ar2 = ar0 + (size_t)16 * NN;
    const __nv_bfloat16* ar3 = ar0 + (size_t)24 * NN;
    const __nv_bfloat16* br[NT];
#pragma unroll
    for (int nt = 0; nt < NT; nt++) {
        int nc = n0 + nt * 8 + g;
        br[nt] = Bm + (size_t)(nc < Nvalid ? nc : Nvalid - 1) * NN;
    }
    float acc[2][NT][4];
#pragma unroll
    for (int r = 0; r < 2; r++)
#pragma unroll
        for (int i = 0; i < NT; i++)
#pragma unroll
            for (int j = 0; j < 4; j++) acc[r][i][j] = 0.f;
#pragma unroll 2
    for (int k0 = 0; k0 < NN; k0 += 16) {
        int kb = k0 + 2 * t;
        unsigned a0 = *(const unsigned*)(ar0 + kb);
        unsigned a1 = *(const unsigned*)(ar1 + kb);
        unsigned a2 = *(const unsigned*)(ar0 + kb + 8);
        unsigned a3 = *(const unsigned*)(ar1 + kb + 8);
        unsigned c0 = *(const unsigned*)(ar2 + kb);
        unsigned c1 = *(const unsigned*)(ar3 + kb);
        unsigned c2 = *(const unsigned*)(ar2 + kb + 8);
        unsigned c3 = *(const unsigned*)(ar3 + kb + 8);
#pragma unroll
        for (int nt = 0; nt < NT; nt++) {
            unsigned b0 = *(const unsigned*)(br[nt] + kb);
            unsigned b1 = *(const unsigned*)(br[nt] + kb + 8);
            mma_bf16(acc[0][nt], a0, a1, a2, a3, b0, b1);
            mma_bf16(acc[1][nt], c0, c1, c2, c3, b0, b1);
        }
    }
#pragma unroll
    for (int r = 0; r < 2; r++) {
        int ra = r1 + r * 16, rb = ra + 8;
#pragma unroll
        for (int nt = 0; nt < NT; nt++) {
            if (n0 + nt * 8 >= Nvalid) continue;
            int n = n0 + nt * 8 + 2 * t;
            float v0 = acc[r][nt][0], v1 = acc[r][nt][1], v2 = acc[r][nt][2], v3 = acc[r][nt][3];
            if (which == 0) { v0 = fmaxf(v0, 0.f); v1 = fmaxf(v1, 0.f); v2 = fmaxf(v2, 0.f); v3 = fmaxf(v3, 0.f); }
            *(float2*)(C + (size_t)ra * Ncols + n) = make_float2(v0, v1);
            *(float2*)(C + (size_t)rb * Ncols + n) = make_float2(v2, v3);
        }
    }
}

// ---------------- combine: out = in + (1-arf)*tmp2 + arf*tmp3 ----------------
__global__ __launch_bounds__(256) void combine_k(const float* __restrict__ in,
                                                 const float* __restrict__ arf) {
    int g = blockIdx.x * 256 + threadIdx.x;
    int p = g % HW, b = g / HW;
    int x = p % WW, y = p / WW;
    float a = __ldg(arf);
    int gy = y / 6, py = y - gy * 6, gx = x / 6, px = x - gx * 6;
    int n = gy * 64 + gx, f = py * 6 + px;
#pragma unroll
    for (int c = 0; c < 2; c++) {
        float t3v = g_t3[(size_t)(c * NN + n) * 144 + b * 36 + f];
        int li = (b * 2 + c) * HW + p;
        g_oimg[li] = in[li] + (1.f - a) * g_tmp2[li] + a * t3v;
    }
}

__device__ __forceinline__ float2 cadd(float2 a, float2 b) { return make_float2(a.x + b.x, a.y + b.y); }
__device__ __forceinline__ float2 csub(float2 a, float2 b) { return make_float2(a.x - b.x, a.y - b.y); }

// ---------------- fwd row FFT; fused z=(-1)^(x+y)*oimg*csm at load ----------------
__global__ __launch_bounds__(192) void fft_row_fwd_k(const float* __restrict__ csr,
                                                     const float* __restrict__ csi) {
    __shared__ float2 sb[384];
    int line = blockIdx.x;
    float2* base = g_k + (size_t)line * 384;
    int tid = threadIdx.x;
    {
        int img = line / HH, y = line % HH;
        int b = img & 3, c = img >> 2;
        const float* o0 = g_oimg + (size_t)(b * 2 + 0) * HW + y * WW;
        const float* o1 = g_oimg + (size_t)(b * 2 + 1) * HW + y * WW;
        const float* cr = csr + (size_t)(b * CCH + c) * HW + y * WW;
        const float* ci = csi + (size_t)(b * CCH + c) * HW + y * WW;
        for (int i = tid; i < 384; i += 192) {
            float orr = o0[i], oii = o1[i];
            float crv = __ldg(cr + i), civ = __ldg(ci + i);
            float sgn = ((i + y) & 1) ? -1.f : 1.f;
            float2 z = make_float2(sgn * (orr * crv - oii * civ), sgn * (orr * civ + oii * crv));
            int r = i % 3, q = i / 3;
            sb[r * 128 + q] = z;
        }
    }
    __syncthreads();
    int r = tid >> 6, bf = tid & 63, off = r << 7;
#pragma unroll
    for (int len = 128; len >= 2; len >>= 1) {
        int h = len >> 1;
        int grp = bf / h, t = bf - grp * h;
        int i1 = off + grp * len + t;
        float2 u = sb[i1], v = sb[i1 + h];
        sb[i1] = cadd(u, v);
        float2 d = csub(u, v);
        float2 w = g_tw128[t * (128 / len)];
        sb[i1 + h] = make_float2(d.x * w.x - d.y * w.y, d.x * w.y + d.y * w.x);
        __syncthreads();
    }
    for (int k = tid; k < 384; k += 192) {
        int k0 = k & 127;
        int rv = __brev((unsigned)k0) >> 25;
        float2 y0 = sb[rv], y1 = sb[128 + rv], y2 = sb[256 + rv];
        float2 c1 = g_tw384[k], c2 = g_tw384[(2 * k) % 384];
        float xr = y0.x + c1.x * y1.x - c1.y * y1.y + c2.x * y2.x - c2.y * y2.y;
        float xi = y0.y + c1.x * y1.y + c1.y * y1.x + c2.x * y2.y + c2.y * y2.x;
        base[k] = make_float2(xr, xi);
    }
}

// ---------------- column FFT; DC=1: apply data consistency at load ----------------
template<int INV, int DC>
__global__ __launch_bounds__(192) void fft_col_k(const int* __restrict__ mask,
                                                 const float* __restrict__ tkr,
                                                 const float* __restrict__ tki) {
    __shared__ float2 sb[8 * 384];
    int img = blockIdx.x / 48, cg = blockIdx.x % 48;
    float2* base = g_k + (size_t)img * HW + cg * 8;
    int tid = threadIdx.x;
    for (int i = tid; i < 3072; i += 192) {
        int col = i & 7, yy = i >> 3;
        float2 Z = base[(size_t)yy * 384 + col];
        if (DC) {
            int gx = cg * 8 + col;
            int p = yy * 384 + gx;
            float mv = (float)__ldg(mask + p);
            float sgn = ((gx + yy) & 1) ? -1.f : 1.f;
            float coef = 384.f * 0.999999f * mv * sgn;
            float om = 1.f - mv;
            size_t gidx = (size_t)img * HW + p;
            Z.x = om * Z.x + coef * __ldg(tkr + gidx);
            Z.y = om * Z.y + coef * __ldg(tki + gidx);
        }
        int r = yy % 3, q = yy / 3;
        sb[col * 384 + r * 128 + q] = Z;
    }
    __syncthreads();
#pragma unroll
    for (int len = 128; len >= 2; len >>= 1) {
        int h = len >> 1;
        for (int widx = tid; widx < 1536; widx += 192) {
            int seg = widx >> 6, bf = widx & 63;
            int boff = (seg / 3) * 384 + (seg % 3) * 128;
            int grp = bf / h, t = bf - grp * h;
            int i1 = boff + grp * len + t;
            float2 u = sb[i1], v = sb[i1 + h];
            sb[i1] = cadd(u, v);
            float2 d = csub(u, v);
            float2 w = g_tw128[t * (128 / len)];
            float wy = INV ? -w.y : w.y;
            sb[i1 + h] = make_float2(d.x * w.x - d.y * wy, d.x * wy + d.y * w.x);
        }
        __syncthreads();
    }
    for (int i = tid; i < 3072; i += 192) {
        int col = i & 7, k = i >> 3;
        int k0 = k & 127;
        int rv = __brev((unsigned)k0) >> 25;
        int cb = col * 384;
        float2 y0 = sb[cb + rv], y1 = sb[cb + 128 + rv], y2 = sb[cb + 256 + rv];
        float2 c1 = g_tw384[k], c2 = g_tw384[(2 * k) % 384];
        float s1 = INV ? -c1.y : c1.y, s2 = INV ? -c2.y : c2.y;
        float xr = y0.x + c1.x * y1.x - s1 * y1.y + c2.x * y2.x - s2 * y2.y;
        float xi = y0.y + c1.x * y1.y + s1 * y1.x + c2.x * y2.y + s2 * y2.x;
        if (INV) { xr *= (1.f / 384.f); xi *= (1.f / 384.f); }
        base[(size_t)k * 384 + col] = make_float2(xr, xi);
    }
}

// ---------------- fused inverse row FFT (12 coils) + coil combine ----------------
__global__ __launch_bounds__(384) void invrow_final_k(const float* __restrict__ csr,
                                                      const float* __restrict__ csi,
                                                      float* __restrict__ out) {
    __shared__ float2 sb[12][384];
    int y = blockIdx.x % HH, b = blockIdx.x / HH;
    int tid = threadIdx.x;
    int r0 = tid % 3, q0 = tid / 3;
#pragma unroll
    for (int c = 0; c < CCH; c++) {
        float2 z = g_k[((size_t)(c * BSZ + b)) * HW + (size_t)y * 384 + tid];
        sb[c][r0 * 128 + q0] = z;
    }
    __syncthreads();
#pragma unroll
    for (int len = 128; len >= 2; len >>= 1) {
        int h = len >> 1;
        for (int widx = tid; widx < 2304; widx += 384) {
            int line = widx / 192, bf = widx % 192;
            int seg = bf >> 6, b6 = bf & 63;
            int grp = b6 / h, t = b6 - grp * h;
            int i1 = seg * 128 + grp * len + t;
            float2 u = sb[line][i1], v = sb[line][i1 + h];
            sb[line][i1] = cadd(u, v);
            float2 d = csub(u, v);
            float2 w = g_tw128[t * (128 / len)];
            sb[line][i1 + h] = make_float2(d.x * w.x + d.y * w.y, -d.x * w.y + d.y * w.x);
        }
        __syncthreads();
    }
    int k = tid;
    int k0 = k & 127;
    int rv = __brev((unsigned)k0) >> 25;
    float2 c1 = g_tw384[k], c2 = g_tw384[(2 * k) % 384];
    float s1 = -c1.y, s2 = -c2.y;
    float rr = 0.f, ri = 0.f;
    const float* crb = csr + (size_t)b * CCH * HW + (size_t)y * WW + k;
    const float* cib = csi + (size_t)b * CCH * HW + (size_t)y * WW + k;
#pragma unroll
    for (int c = 0; c < CCH; c++) {
        float2 y0 = sb[c][rv], y1 = sb[c][128 + rv], y2 = sb[c][256 + rv];
        float xr = (y0.x + c1.x * y1.x - s1 * y1.y + c2.x * y2.x - s2 * y2.y) * (1.f / 384.f);
        float xi = (y0.y + c1.x * y1.y + s1 * y1.x + c2.x * y2.y + s2 * y2.x) * (1.f / 384.f);
        float cr = __ldg(crb + (size_t)c * HW);
        float ci = __ldg(cib + (size_t)c * HW);
        rr += xr * cr + xi * ci;
        ri += xi * cr - xr * ci;
    }
    float sgn = ((k + y) & 1) ? -1.f : 1.f;
    out[(size_t)(b * 2 + 0) * HW + (size_t)y * WW + k] = sgn * rr;
    out[(size_t)(b * 2 + 1) * HW + (size_t)y * WW + k] = sgn * ri;
}

// ---------------- launch ----------------
extern "C" void kernel_launch(void* const* d_in, const int* in_sizes, int n_in,
                              void* d_out, int out_size) {
    (void)in_sizes; (void)n_in; (void)out_size;
    const float* input = (const float*)d_in[0];
    const float* adj   = (const float*)d_in[1];
    const int*   mask  = (const int*)  d_in[2];
    const float* csr   = (const float*)d_in[3];
    const float* csi   = (const float*)d_in[4];
    const float* tkr   = (const float*)d_in[5];
    const float* tki   = (const float*)d_in[6];
    const float* W1    = (const float*)d_in[7];
    const float* W3    = (const float*)d_in[8];
    const float* arf   = (const float*)d_in[9];
    const float* cw1   = (const float*)d_in[10];
    const float* cb1   = (const float*)d_in[11];
    const float* cw2   = (const float*)d_in[12];
    const float* cb2   = (const float*)d_in[13];
    const float* cw3   = (const float*)d_in[14];
    const float* cb3   = (const float*)d_in[15];
    float* out = (float*)d_out;

    // Order chosen so conv2_mma is launch index 3 (the ncu-captured slot).
    prep_w_k<<<144, 256>>>(cw2, cw3);                 // 0
    conv1_k<<<4608, 256>>>(input, cw1, cb1);          // 1
    adj_cvt_k<<<32768, 256>>>(adj);                   // 2
    conv2_mma<<<dim3(6, 192, 4), 128>>>(cb2);         // 3  <-- profiled
    conv3_mma<<<dim3(6, 192, 4), 128>>>(cb3);         // 4

    // GCN branch
    gcn_s_k<<<256, 128>>>(input, W1);
    gemm_mma<8><<<dim3(4, 32, 2), 128>>>(0, 256);     // g = relu(adj @ s)
    gcn_s3_k<<<256, 128>>>(W3);
    gemm_mma<8><<<dim3(3, 32, 2), 128>>>(1, 144);     // t3, clamped tail

    // combine + FFT chain
    combine_k<<<2304, 256>>>(input, arf);
    init_tw_k<<<1, 384>>>();
    fft_row_fwd_k<<<48 * 384, 192>>>(csr, csi);
    fft_col_k<0, 0><<<48 * 48, 192>>>(nullptr, nullptr, nullptr);
    fft_col_k<1, 1><<<48 * 48, 192>>>(mask, tkr, tki);
    invrow_final_k<<<4 * 384, 384>>>(csr, csi, out);
}